// round 3
// baseline (speedup 1.0000x reference)
#include <cuda_runtime.h>
#include <math.h>

// Problem constants
#define B_  32
#define S_  128
#define T_  64
#define E_  256
#define H_  512      // encoder hidden
#define V_  32000
#define GH  2048     // 4*H encoder gates
#define DH  1024     // decoder hidden (2H)
#define DG  4096     // 4*DH decoder gates
#define TD  63       // T-1 decoder steps

// ---------------- scratch (static device globals; no runtime allocation) ----------------
// Pregates stored TRANSPOSED: [t][gate_n][b]
__device__ float g_pre_fT[(size_t)S_ * GH * B_];
__device__ float g_pre_bT[(size_t)S_ * GH * B_];
__device__ float g_dec_preT[(size_t)TD * DG * B_];
__device__ float g_dec_hs[(size_t)TD * B_ * DH];     // row-major for final GEMM
// States transposed [cell][b]
__device__ float g_enc_hT[2][2][H_ * B_];            // [dir][parity]
__device__ float g_enc_cT[2][H_ * B_];
__device__ float g_dec_hT[2][DH * B_];
__device__ float g_dec_cT[DH * B_];
__device__ int   g_enc_rowidx[S_ * B_];
__device__ int   g_dec_rowidx[TD * B_];

// ---------------- prep: zero states, build gather indices, zero out[:,0,:] ----------------
__global__ void prep_k(const int* __restrict__ src, const int* __restrict__ trg,
                       float* __restrict__ out)
{
    long idx = (long)blockIdx.x * blockDim.x + threadIdx.x;
    const long N0 = (long)B_ * V_;
    if (idx < N0) {
        long b = idx / V_, v = idx - b * V_;
        out[(size_t)b * T_ * V_ + v] = 0.f;   // out[:,0,:] = 0
        return;
    }
    idx -= N0;
    if (idx < 2 * H_ * B_) { g_enc_hT[idx >> 14][0][idx & 16383] = 0.f; return; }
    idx -= 2 * H_ * B_;
    if (idx < 2 * H_ * B_) { g_enc_cT[idx >> 14][idx & 16383] = 0.f; return; }
    idx -= 2 * H_ * B_;
    if (idx < S_ * B_) {
        int t = (int)(idx / B_), b = (int)(idx % B_);
        g_enc_rowidx[idx] = src[b * S_ + t];
        return;
    }
    idx -= S_ * B_;
    if (idx < TD * B_) {
        int t = (int)(idx / B_), b = (int)(idx % B_);
        g_dec_rowidx[idx] = trg[b * T_ + t];
        return;
    }
}

// ---------------- generic SGEMM: C[m][n] = bias[n] + sum_k A[row(m)][k] * W[n][k] ----------
// OUT_MODE 0: row-major C[m][n]
// OUT_MODE 1: final-logits remap: row m=t*32+b -> out row (b*T + t + 1)
// OUT_MODE 2: pregate transpose: C[((m/32)*N + n)*32 + (m%32)]
template <int OUT_MODE>
__global__ void sgemm_k(const float* __restrict__ A, const float* __restrict__ W,
                        const float* __restrict__ bias, const int* __restrict__ rowidx,
                        float* __restrict__ C, int M, int N, int K)
{
    __shared__ float As[16][128];
    __shared__ float Bs[16][128];
    const int tid = threadIdx.x;
    const int m0 = blockIdx.y * 128;
    const int n0 = blockIdx.x * 128;

    const int lm = tid & 127;
    const int lq = tid >> 7;             // 0 or 1
    int mm = m0 + lm; if (mm >= M) mm = M - 1;
    const int arow = rowidx ? rowidx[mm] : mm;
    const float* aptr = A + (size_t)arow * K;
    const float* bptr = W + (size_t)(n0 + lm) * K;

    const int tx = tid & 15, ty = tid >> 4;
    float acc[8][8];
#pragma unroll
    for (int i = 0; i < 8; i++)
#pragma unroll
        for (int j = 0; j < 8; j++) acc[i][j] = 0.f;

    for (int k0 = 0; k0 < K; k0 += 16) {
        float4 a0 = *(const float4*)(aptr + k0 + 4 * lq);
        float4 a1 = *(const float4*)(aptr + k0 + 4 * lq + 8);
        float4 b0 = *(const float4*)(bptr + k0 + 4 * lq);
        float4 b1 = *(const float4*)(bptr + k0 + 4 * lq + 8);
        __syncthreads();
        As[4 * lq + 0][lm] = a0.x; As[4 * lq + 1][lm] = a0.y;
        As[4 * lq + 2][lm] = a0.z; As[4 * lq + 3][lm] = a0.w;
        As[4 * lq + 8][lm] = a1.x; As[4 * lq + 9][lm] = a1.y;
        As[4 * lq + 10][lm] = a1.z; As[4 * lq + 11][lm] = a1.w;
        Bs[4 * lq + 0][lm] = b0.x; Bs[4 * lq + 1][lm] = b0.y;
        Bs[4 * lq + 2][lm] = b0.z; Bs[4 * lq + 3][lm] = b0.w;
        Bs[4 * lq + 8][lm] = b1.x; Bs[4 * lq + 9][lm] = b1.y;
        Bs[4 * lq + 10][lm] = b1.z; Bs[4 * lq + 11][lm] = b1.w;
        __syncthreads();
#pragma unroll
        for (int k = 0; k < 16; k++) {
            float ar[8], br[8];
            *(float4*)&ar[0] = *(const float4*)&As[k][ty * 8];
            *(float4*)&ar[4] = *(const float4*)&As[k][ty * 8 + 4];
            *(float4*)&br[0] = *(const float4*)&Bs[k][tx * 8];
            *(float4*)&br[4] = *(const float4*)&Bs[k][tx * 8 + 4];
#pragma unroll
            for (int i = 0; i < 8; i++)
#pragma unroll
                for (int j = 0; j < 8; j++) acc[i][j] += ar[i] * br[j];
        }
    }

#pragma unroll
    for (int i = 0; i < 8; i++) {
        int m = m0 + ty * 8 + i;
        if (m >= M) break;
        const float* bp = bias + n0 + tx * 8;
        if (OUT_MODE == 2) {
            int t = m >> 5, b = m & 31;
#pragma unroll
            for (int j = 0; j < 8; j++) {
                int n = n0 + tx * 8 + j;
                C[((size_t)t * N + n) * B_ + b] = acc[i][j] + bp[j];
            }
        } else {
            size_t row;
            if (OUT_MODE == 1) { int b = m & 31; int t = m >> 5; row = (size_t)(b * T_ + t + 1); }
            else               { row = (size_t)m; }
            float* cp = C + row * (size_t)N + n0 + tx * 8;
#pragma unroll
            for (int j = 0; j < 8; j++) cp[j] = acc[i][j] + bp[j];
        }
    }
}

// ---------------- encoder LSTM step: warp = cell, lane = batch ----------------
// grid (H_/8, 2 dirs), 256 threads (8 warps). Whh read ONCE per step per dir.
__global__ void enc_step_k(const float* __restrict__ Whh_f,
                           const float* __restrict__ Whh_b, int s)
{
    extern __shared__ float shT[];   // H_ * 32 floats = 64KB
    const int dir = blockIdx.y;
    const float* Whh = dir ? Whh_b : Whh_f;
    const int t = dir ? (S_ - 1 - s) : s;
    const float* hT_in = g_enc_hT[dir][s & 1];
    float* hT_out = g_enc_hT[dir][(s + 1) & 1];
    float* cT = g_enc_cT[dir];

    // stage full transposed h into smem (coalesced float4)
    {
        const float4* s4 = (const float4*)hT_in;
        float4* d4 = (float4*)shT;
        for (int i = threadIdx.x; i < H_ * B_ / 4; i += 256) d4[i] = s4[i];
    }
    __syncthreads();

    const int w = threadIdx.x >> 5, lane = threadIdx.x & 31;
    const int j = blockIdx.x * 8 + w;

    const float4* wi = (const float4*)(Whh + (size_t)j * H_);
    const float4* wf = (const float4*)(Whh + (size_t)(H_ + j) * H_);
    const float4* wg = (const float4*)(Whh + (size_t)(2 * H_ + j) * H_);
    const float4* wo = (const float4*)(Whh + (size_t)(3 * H_ + j) * H_);

    const float* preT = (dir ? g_pre_bT : g_pre_fT) + (size_t)t * GH * B_;
    float ai = preT[(size_t)(0 * H_ + j) * B_ + lane];
    float af = preT[(size_t)(1 * H_ + j) * B_ + lane];
    float ag = preT[(size_t)(2 * H_ + j) * B_ + lane];
    float ao = preT[(size_t)(3 * H_ + j) * B_ + lane];

#pragma unroll 4
    for (int k4 = 0; k4 < H_ / 4; k4++) {
        float4 a = wi[k4], f = wf[k4], g = wg[k4], o = wo[k4];
        float h0 = shT[(k4 * 4 + 0) * B_ + lane];
        float h1 = shT[(k4 * 4 + 1) * B_ + lane];
        float h2 = shT[(k4 * 4 + 2) * B_ + lane];
        float h3 = shT[(k4 * 4 + 3) * B_ + lane];
        ai += h0 * a.x + h1 * a.y + h2 * a.z + h3 * a.w;
        af += h0 * f.x + h1 * f.y + h2 * f.z + h3 * f.w;
        ag += h0 * g.x + h1 * g.y + h2 * g.z + h3 * g.w;
        ao += h0 * o.x + h1 * o.y + h2 * o.z + h3 * o.w;
    }
    float iv = 1.f / (1.f + expf(-ai));
    float fv = 1.f / (1.f + expf(-af));
    float gv = tanhf(ag);
    float ov = 1.f / (1.f + expf(-ao));
    float cv = fv * cT[(size_t)j * B_ + lane] + iv * gv;
    cT[(size_t)j * B_ + lane] = cv;
    hT_out[(size_t)j * B_ + lane] = ov * tanhf(cv);
}

// ---------------- decoder init: transposed concat of enc final states ----------------
__global__ void dec_init_k()
{
    int idx = blockIdx.x * blockDim.x + threadIdx.x;  // 0 .. 65535
    int which = idx >> 15;       // 0: h, 1: c
    int i = idx & 32767;         // j*32 + b over DH*32
    int j = i >> 5, b = i & 31;
    float v;
    if (j < H_) v = which ? g_enc_cT[0][j * B_ + b] : g_enc_hT[0][0][j * B_ + b];
    else        v = which ? g_enc_cT[1][(j - H_) * B_ + b] : g_enc_hT[1][0][(j - H_) * B_ + b];
    if (which) g_dec_cT[j * B_ + b] = v;
    else       g_dec_hT[0][j * B_ + b] = v;
}

// ---------------- decoder LSTM step: warp = cell, lane = batch ----------------
// grid (DH/8), 256 threads. Needs 128KB dynamic smem.
__global__ void dec_step_k(const float* __restrict__ Whh, int t)
{
    extern __shared__ float shT[];   // DH * 32 floats = 128KB
    const float* hT_in = g_dec_hT[t & 1];
    float* hT_out = g_dec_hT[(t + 1) & 1];

    {
        const float4* s4 = (const float4*)hT_in;
        float4* d4 = (float4*)shT;
        for (int i = threadIdx.x; i < DH * B_ / 4; i += 256) d4[i] = s4[i];
    }
    __syncthreads();

    const int w = threadIdx.x >> 5, lane = threadIdx.x & 31;
    const int j = blockIdx.x * 8 + w;

    const float4* wi = (const float4*)(Whh + (size_t)j * DH);
    const float4* wf = (const float4*)(Whh + (size_t)(DH + j) * DH);
    const float4* wg = (const float4*)(Whh + (size_t)(2 * DH + j) * DH);
    const float4* wo = (const float4*)(Whh + (size_t)(3 * DH + j) * DH);

    const float* preT = g_dec_preT + (size_t)t * DG * B_;
    float ai = preT[(size_t)(0 * DH + j) * B_ + lane];
    float af = preT[(size_t)(1 * DH + j) * B_ + lane];
    float ag = preT[(size_t)(2 * DH + j) * B_ + lane];
    float ao = preT[(size_t)(3 * DH + j) * B_ + lane];

#pragma unroll 4
    for (int k4 = 0; k4 < DH / 4; k4++) {
        float4 a = wi[k4], f = wf[k4], g = wg[k4], o = wo[k4];
        float h0 = shT[(k4 * 4 + 0) * B_ + lane];
        float h1 = shT[(k4 * 4 + 1) * B_ + lane];
        float h2 = shT[(k4 * 4 + 2) * B_ + lane];
        float h3 = shT[(k4 * 4 + 3) * B_ + lane];
        ai += h0 * a.x + h1 * a.y + h2 * a.z + h3 * a.w;
        af += h0 * f.x + h1 * f.y + h2 * f.z + h3 * f.w;
        ag += h0 * g.x + h1 * g.y + h2 * g.z + h3 * g.w;
        ao += h0 * o.x + h1 * o.y + h2 * o.z + h3 * o.w;
    }
    float iv = 1.f / (1.f + expf(-ai));
    float fv = 1.f / (1.f + expf(-af));
    float gv = tanhf(ag);
    float ov = 1.f / (1.f + expf(-ao));
    float cv = fv * g_dec_cT[(size_t)j * B_ + lane] + iv * gv;
    float hv = ov * tanhf(cv);
    g_dec_cT[(size_t)j * B_ + lane] = cv;
    hT_out[(size_t)j * B_ + lane] = hv;
    // row-major copy for final GEMM (strided scalar store, tiny volume)
    g_dec_hs[((size_t)t * B_ + lane) * DH + j] = hv;
}

// ---------------- launch ----------------
extern "C" void kernel_launch(void* const* d_in, const int* in_sizes, int n_in,
                              void* d_out, int out_size)
{
    (void)in_sizes; (void)n_in; (void)out_size;
    const int*   src     = (const int*)d_in[0];
    const int*   trg     = (const int*)d_in[1];
    const float* enc_emb = (const float*)d_in[2];
    const float* dec_emb = (const float*)d_in[3];
    const float* eWih_f  = (const float*)d_in[4];
    const float* eWhh_f  = (const float*)d_in[5];
    const float* eb_f    = (const float*)d_in[6];
    const float* eWih_b  = (const float*)d_in[7];
    const float* eWhh_b  = (const float*)d_in[8];
    const float* eb_b    = (const float*)d_in[9];
    const float* dWih    = (const float*)d_in[10];
    const float* dWhh    = (const float*)d_in[11];
    const float* db      = (const float*)d_in[12];
    const float* fcW     = (const float*)d_in[13];
    const float* fcb     = (const float*)d_in[14];
    float* out = (float*)d_out;

    static int configured = 0;
    if (!configured) {
        cudaFuncSetAttribute(enc_step_k, cudaFuncAttributeMaxDynamicSharedMemorySize,
                             H_ * B_ * 4);
        cudaFuncSetAttribute(dec_step_k, cudaFuncAttributeMaxDynamicSharedMemorySize,
                             DH * B_ * 4);
        configured = 1;
    }

    void *p_pre_fT, *p_pre_bT, *p_dec_preT, *p_dec_hs, *p_enc_ri, *p_dec_ri;
    cudaGetSymbolAddress(&p_pre_fT, g_pre_fT);
    cudaGetSymbolAddress(&p_pre_bT, g_pre_bT);
    cudaGetSymbolAddress(&p_dec_preT, g_dec_preT);
    cudaGetSymbolAddress(&p_dec_hs, g_dec_hs);
    cudaGetSymbolAddress(&p_enc_ri, g_enc_rowidx);
    cudaGetSymbolAddress(&p_dec_ri, g_dec_rowidx);

    long total = (long)B_ * V_ + 2L * H_ * B_ + 2L * H_ * B_ + (long)S_ * B_ + (long)TD * B_;
    prep_k<<<(unsigned)((total + 255) / 256), 256>>>(src, trg, out);

    // pregate GEMMs -> transposed [t][gate][b]
    sgemm_k<2><<<dim3(GH / 128, (S_ * B_) / 128), 256>>>(
        enc_emb, eWih_f, eb_f, (const int*)p_enc_ri, (float*)p_pre_fT, S_ * B_, GH, E_);
    sgemm_k<2><<<dim3(GH / 128, (S_ * B_) / 128), 256>>>(
        enc_emb, eWih_b, eb_b, (const int*)p_enc_ri, (float*)p_pre_bT, S_ * B_, GH, E_);
    sgemm_k<2><<<dim3(DG / 128, (TD * B_ + 127) / 128), 256>>>(
        dec_emb, dWih, db, (const int*)p_dec_ri, (float*)p_dec_preT, TD * B_, DG, E_);

    // encoder recurrence (fwd + bwd fused per step)
    for (int s = 0; s < S_; s++)
        enc_step_k<<<dim3(H_ / 8, 2), 256, H_ * B_ * 4>>>(eWhh_f, eWhh_b, s);

    // decoder init + recurrence
    dec_init_k<<<256, 256>>>();
    for (int t = 0; t < TD; t++)
        dec_step_k<<<DH / 8, 256, DH * B_ * 4>>>(dWhh, t);

    // final logits GEMM, remapped into out[b][t+1][:]
    sgemm_k<1><<<dim3(V_ / 128, (TD * B_ + 127) / 128), 256>>>(
        (const float*)p_dec_hs, fcW, fcb, nullptr, out, TD * B_, V_, DH);
}

// round 4
// speedup vs baseline: 1.0751x; 1.0751x over previous
#include <cuda_runtime.h>
#include <cuda_bf16.h>
#include <math.h>
#include <stdint.h>

#define B_  32
#define S_  128
#define T_  64
#define E_  256
#define H_  512
#define V_  32000
#define GH  2048
#define DH  1024
#define DG  4096
#define TD  63
#define MROWS 2016
#define MPAD  2048
#define NCH 96      // 3 blocks x 32 chunks of K=32

// ---------------- scratch ----------------
__device__ float g_pre_fT[(size_t)S_ * GH * B_];
__device__ float g_pre_bT[(size_t)S_ * GH * B_];
__device__ float g_dec_preT[(size_t)TD * DG * B_];
__device__ float g_enc_hT[2][2][H_ * B_];
__device__ float g_enc_cT[2][H_ * B_];
__device__ float g_dec_hT[2][DH * B_];
__device__ int   g_enc_rowidx[S_ * B_];
__device__ int   g_dec_rowidx[TD * B_];
__device__ __nv_bfloat16 g_Abig[(size_t)MPAD * 2048];   // [hi(1024) | lo(1024)]
__device__ __nv_bfloat16 g_Wbig[(size_t)V_ * 2048];     // [hi | lo]
__device__ unsigned g_flagsA[128];
__device__ unsigned g_flagsB[128];

// ---------------- grid barrier ----------------
__device__ __forceinline__ void grid_barrier(unsigned* flags, unsigned target)
{
    __threadfence();
    __syncthreads();
    if (threadIdx.x == 0)
        asm volatile("st.release.gpu.u32 [%0], %1;" :: "l"(flags + blockIdx.x),
                     "r"(target) : "memory");
    if (threadIdx.x < 128) {
        unsigned v;
        do {
            asm volatile("ld.acquire.gpu.u32 %0, [%1];" : "=r"(v)
                         : "l"(flags + threadIdx.x) : "memory");
        } while (v < target);
    }
    __syncthreads();
}

// ---------------- prep ----------------
__global__ void prep_k(const int* __restrict__ src, const int* __restrict__ trg,
                       float* __restrict__ out)
{
    long idx = (long)blockIdx.x * blockDim.x + threadIdx.x;
    const long N0 = (long)B_ * V_;
    if (idx < N0) {
        long b = idx / V_, v = idx - b * V_;
        out[(size_t)b * T_ * V_ + v] = 0.f;
        return;
    }
    idx -= N0;
    if (idx < 2 * H_ * B_) { g_enc_hT[idx >> 14][0][idx & 16383] = 0.f; return; }
    idx -= 2 * H_ * B_;
    if (idx < S_ * B_) {
        int t = (int)(idx / B_), b = (int)(idx % B_);
        g_enc_rowidx[idx] = src[b * S_ + t];
        return;
    }
    idx -= S_ * B_;
    if (idx < TD * B_) {
        int t = (int)(idx / B_), b = (int)(idx % B_);
        g_dec_rowidx[idx] = trg[b * T_ + t];
        return;
    }
    idx -= TD * B_;
    if (idx < 128) { g_flagsA[idx] = 0; return; }
    idx -= 128;
    if (idx < 128) { g_flagsB[idx] = 0; return; }
    idx -= 128;
    if (idx < (MPAD - MROWS) * 2048) {   // zero A pad rows
        g_Abig[(size_t)(MROWS + (idx >> 11)) * 2048 + (idx & 2047)] = __float2bfloat16(0.f);
        return;
    }
}

// ---------------- W split conversion ----------------
__global__ void wconv_k(const float* __restrict__ fcW)
{
    size_t i = (size_t)blockIdx.x * 256 + threadIdx.x;     // over V_*256 float4s
    if (i >= (size_t)V_ * 256) return;
    size_t n = i >> 8; int k4 = (int)(i & 255);
    float4 v = __ldcg((const float4*)fcW + i);
    __nv_bfloat16 h0 = __float2bfloat16(v.x), h1 = __float2bfloat16(v.y);
    __nv_bfloat16 h2 = __float2bfloat16(v.z), h3 = __float2bfloat16(v.w);
    __nv_bfloat16 l0 = __float2bfloat16(v.x - __bfloat162float(h0));
    __nv_bfloat16 l1 = __float2bfloat16(v.y - __bfloat162float(h1));
    __nv_bfloat16 l2 = __float2bfloat16(v.z - __bfloat162float(h2));
    __nv_bfloat16 l3 = __float2bfloat16(v.w - __bfloat162float(h3));
    __nv_bfloat162* dh = (__nv_bfloat162*)(g_Wbig + n * 2048 + k4 * 4);
    __nv_bfloat162* dl = (__nv_bfloat162*)(g_Wbig + n * 2048 + 1024 + k4 * 4);
    __nv_bfloat162 a; a.x = h0; a.y = h1; dh[0] = a;
    __nv_bfloat162 b; b.x = h2; b.y = h3; dh[1] = b;
    __nv_bfloat162 c; c.x = l0; c.y = l1; dl[0] = c;
    __nv_bfloat162 d; d.x = l2; d.y = l3; dl[1] = d;
}

// ---------------- pregate SGEMM (transposed output [t][gate][b]) ----------------
__global__ void sgemm_k(const float* __restrict__ A, const float* __restrict__ W,
                        const float* __restrict__ bias, const int* __restrict__ rowidx,
                        float* __restrict__ C, int M, int N, int K)
{
    __shared__ float As[16][128];
    __shared__ float Bs[16][128];
    const int tid = threadIdx.x;
    const int m0 = blockIdx.y * 128, n0 = blockIdx.x * 128;
    const int lm = tid & 127, lq = tid >> 7;
    int mm = m0 + lm; if (mm >= M) mm = M - 1;
    const float* aptr = A + (size_t)rowidx[mm] * K;
    const float* bptr = W + (size_t)(n0 + lm) * K;
    const int tx = tid & 15, ty = tid >> 4;
    float acc[8][8];
#pragma unroll
    for (int i = 0; i < 8; i++)
#pragma unroll
        for (int j = 0; j < 8; j++) acc[i][j] = 0.f;

    for (int k0 = 0; k0 < K; k0 += 16) {
        float4 a0 = *(const float4*)(aptr + k0 + 4 * lq);
        float4 a1 = *(const float4*)(aptr + k0 + 4 * lq + 8);
        float4 b0 = *(const float4*)(bptr + k0 + 4 * lq);
        float4 b1 = *(const float4*)(bptr + k0 + 4 * lq + 8);
        __syncthreads();
        As[4 * lq + 0][lm] = a0.x; As[4 * lq + 1][lm] = a0.y;
        As[4 * lq + 2][lm] = a0.z; As[4 * lq + 3][lm] = a0.w;
        As[4 * lq + 8][lm] = a1.x; As[4 * lq + 9][lm] = a1.y;
        As[4 * lq + 10][lm] = a1.z; As[4 * lq + 11][lm] = a1.w;
        Bs[4 * lq + 0][lm] = b0.x; Bs[4 * lq + 1][lm] = b0.y;
        Bs[4 * lq + 2][lm] = b0.z; Bs[4 * lq + 3][lm] = b0.w;
        Bs[4 * lq + 8][lm] = b1.x; Bs[4 * lq + 9][lm] = b1.y;
        Bs[4 * lq + 10][lm] = b1.z; Bs[4 * lq + 11][lm] = b1.w;
        __syncthreads();
#pragma unroll
        for (int k = 0; k < 16; k++) {
            float ar[8], br[8];
            *(float4*)&ar[0] = *(const float4*)&As[k][ty * 8];
            *(float4*)&ar[4] = *(const float4*)&As[k][ty * 8 + 4];
            *(float4*)&br[0] = *(const float4*)&Bs[k][tx * 8];
            *(float4*)&br[4] = *(const float4*)&Bs[k][tx * 8 + 4];
#pragma unroll
            for (int i = 0; i < 8; i++)
#pragma unroll
                for (int j = 0; j < 8; j++) acc[i][j] += ar[i] * br[j];
        }
    }
#pragma unroll
    for (int i = 0; i < 8; i++) {
        int m = m0 + ty * 8 + i;
        if (m >= M) break;
        int t = m >> 5, b = m & 31;
        const float* bp = bias + n0 + tx * 8;
#pragma unroll
        for (int j = 0; j < 8; j++)
            C[((size_t)t * N + (n0 + tx * 8 + j)) * B_ + b] = acc[i][j] + bp[j];
    }
}

// ---------------- persistent encoder (all S_ steps, both dirs) ----------------
__global__ void enc_persist_k(const float* __restrict__ Whh_f,
                              const float* __restrict__ Whh_b)
{
    extern __shared__ float shT[];   // 64KB
    const int dir = blockIdx.x >> 6, cb = blockIdx.x & 63;
    const int w = threadIdx.x >> 5, lane = threadIdx.x & 31;
    const int j = cb * 8 + w;
    const float* Whh = dir ? Whh_b : Whh_f;
    const float* preBase = dir ? g_pre_bT : g_pre_fT;
    const float4* wi = (const float4*)(Whh + (size_t)j * H_);
    const float4* wf = (const float4*)(Whh + (size_t)(H_ + j) * H_);
    const float4* wg = (const float4*)(Whh + (size_t)(2 * H_ + j) * H_);
    const float4* wo = (const float4*)(Whh + (size_t)(3 * H_ + j) * H_);
    float cst = 0.f;

    for (int s = 0; s < S_; s++) {
        const float4* s4 = (const float4*)g_enc_hT[dir][s & 1];
        float4* d4 = (float4*)shT;
        for (int i = threadIdx.x; i < H_ * B_ / 4; i += 256) d4[i] = __ldcg(s4 + i);
        __syncthreads();
        const int t = dir ? (S_ - 1 - s) : s;
        const float* preT = preBase + (size_t)t * GH * B_;
        float ai = __ldcg(preT + (size_t)(0 * H_ + j) * B_ + lane);
        float af = __ldcg(preT + (size_t)(1 * H_ + j) * B_ + lane);
        float ag = __ldcg(preT + (size_t)(2 * H_ + j) * B_ + lane);
        float ao = __ldcg(preT + (size_t)(3 * H_ + j) * B_ + lane);
#pragma unroll 4
        for (int k4 = 0; k4 < H_ / 4; k4++) {
            float4 a = wi[k4], f = wf[k4], g = wg[k4], o = wo[k4];
            float h0 = shT[(k4 * 4 + 0) * B_ + lane];
            float h1 = shT[(k4 * 4 + 1) * B_ + lane];
            float h2 = shT[(k4 * 4 + 2) * B_ + lane];
            float h3 = shT[(k4 * 4 + 3) * B_ + lane];
            ai += h0 * a.x + h1 * a.y + h2 * a.z + h3 * a.w;
            af += h0 * f.x + h1 * f.y + h2 * f.z + h3 * f.w;
            ag += h0 * g.x + h1 * g.y + h2 * g.z + h3 * g.w;
            ao += h0 * o.x + h1 * o.y + h2 * o.z + h3 * o.w;
        }
        float iv = 1.f / (1.f + expf(-ai));
        float fv = 1.f / (1.f + expf(-af));
        float gv = tanhf(ag);
        float ov = 1.f / (1.f + expf(-ao));
        cst = fv * cst + iv * gv;
        g_enc_hT[dir][(s + 1) & 1][(size_t)j * B_ + lane] = ov * tanhf(cst);
        if (s == S_ - 1) g_enc_cT[dir][(size_t)j * B_ + lane] = cst;
        grid_barrier(g_flagsA, s + 1);
    }
}

// ---------------- persistent decoder ----------------
__global__ void dec_persist_k(const float* __restrict__ Whh)
{
    extern __shared__ float shT[];   // 128KB
    const int w = threadIdx.x >> 5, lane = threadIdx.x & 31;
    const int j = blockIdx.x * 8 + w;
    float cst, h0v;
    if (j < H_) { cst = g_enc_cT[0][j * B_ + lane]; h0v = g_enc_hT[0][0][j * B_ + lane]; }
    else { cst = g_enc_cT[1][(j - H_) * B_ + lane]; h0v = g_enc_hT[1][0][(j - H_) * B_ + lane]; }
    g_dec_hT[0][(size_t)j * B_ + lane] = h0v;
    grid_barrier(g_flagsB, 1);

    const float4* wi = (const float4*)(Whh + (size_t)j * DH);
    const float4* wf = (const float4*)(Whh + (size_t)(DH + j) * DH);
    const float4* wg = (const float4*)(Whh + (size_t)(2 * DH + j) * DH);
    const float4* wo = (const float4*)(Whh + (size_t)(3 * DH + j) * DH);

    for (int t = 0; t < TD; t++) {
        const float4* s4 = (const float4*)g_dec_hT[t & 1];
        float4* d4 = (float4*)shT;
        for (int i = threadIdx.x; i < DH * B_ / 4; i += 256) d4[i] = __ldcg(s4 + i);
        __syncthreads();
        const float* preT = g_dec_preT + (size_t)t * DG * B_;
        float ai = __ldcg(preT + (size_t)(0 * DH + j) * B_ + lane);
        float af = __ldcg(preT + (size_t)(1 * DH + j) * B_ + lane);
        float ag = __ldcg(preT + (size_t)(2 * DH + j) * B_ + lane);
        float ao = __ldcg(preT + (size_t)(3 * DH + j) * B_ + lane);
#pragma unroll 4
        for (int k4 = 0; k4 < DH / 4; k4++) {
            float4 a = wi[k4], f = wf[k4], g = wg[k4], o = wo[k4];
            float h0 = shT[(k4 * 4 + 0) * B_ + lane];
            float h1 = shT[(k4 * 4 + 1) * B_ + lane];
            float h2 = shT[(k4 * 4 + 2) * B_ + lane];
            float h3 = shT[(k4 * 4 + 3) * B_ + lane];
            ai += h0 * a.x + h1 * a.y + h2 * a.z + h3 * a.w;
            af += h0 * f.x + h1 * f.y + h2 * f.z + h3 * f.w;
            ag += h0 * g.x + h1 * g.y + h2 * g.z + h3 * g.w;
            ao += h0 * o.x + h1 * o.y + h2 * o.z + h3 * o.w;
        }
        float iv = 1.f / (1.f + expf(-ai));
        float fv = 1.f / (1.f + expf(-af));
        float gv = tanhf(ag);
        float ov = 1.f / (1.f + expf(-ao));
        cst = fv * cst + iv * gv;
        float hv = ov * tanhf(cst);
        g_dec_hT[(t + 1) & 1][(size_t)j * B_ + lane] = hv;
        // split-bf16 A row for final GEMM: m = t*32 + b
        size_t m = (size_t)t * B_ + lane;
        __nv_bfloat16 hi = __float2bfloat16(hv);
        g_Abig[m * 2048 + j] = hi;
        g_Abig[m * 2048 + 1024 + j] = __float2bfloat16(hv - __bfloat162float(hi));
        grid_barrier(g_flagsB, t + 2);
    }
}

// ---------------- split-bf16 tensor GEMM (final logits) ----------------
__device__ __forceinline__ void ldsm4(uint32_t* r, uint32_t addr)
{
    asm volatile("ldmatrix.sync.aligned.m8n8.x4.shared.b16 {%0,%1,%2,%3}, [%4];"
                 : "=r"(r[0]), "=r"(r[1]), "=r"(r[2]), "=r"(r[3]) : "r"(addr));
}
__device__ __forceinline__ void mma16816(float* d, const uint32_t* a, uint32_t b0, uint32_t b1)
{
    asm volatile("mma.sync.aligned.m16n8k16.row.col.f32.bf16.bf16.f32 "
                 "{%0,%1,%2,%3},{%4,%5,%6,%7},{%8,%9},{%0,%1,%2,%3};"
                 : "+f"(d[0]), "+f"(d[1]), "+f"(d[2]), "+f"(d[3])
                 : "r"(a[0]), "r"(a[1]), "r"(a[2]), "r"(a[3]), "r"(b0), "r"(b1));
}

__global__ __launch_bounds__(256, 2)
void bgemm_k(const float* __restrict__ bias, float* __restrict__ out)
{
    __shared__ __align__(16) unsigned char smem[40960];  // A:2x10240, B:2x10240
    const int tid = threadIdx.x, lane = tid & 31, w = tid >> 5;
    const int wm = w >> 2, wn = w & 3;
    const int n0 = blockIdx.x * 128, m0 = blockIdx.y * 128;

    float acc[4][4][4];
#pragma unroll
    for (int a = 0; a < 4; a++)
#pragma unroll
        for (int b = 0; b < 4; b++)
#pragma unroll
            for (int c = 0; c < 4; c++) acc[a][b][c] = 0.f;

    const int rowL = tid >> 2, c16 = tid & 3;            // loader: rows rowL, rowL+64
    const __nv_bfloat16* Ag0 = g_Abig + (size_t)(m0 + rowL) * 2048 + c16 * 8;
    const __nv_bfloat16* Ag1 = Ag0 + (size_t)64 * 2048;
    const __nv_bfloat16* Wg0 = g_Wbig + (size_t)(n0 + rowL) * 2048 + c16 * 8;
    const __nv_bfloat16* Wg1 = Wg0 + (size_t)64 * 2048;
    unsigned char* SA = smem;
    unsigned char* SB = smem + 20480;
    unsigned char* sa0 = SA + rowL * 80 + c16 * 16;
    unsigned char* sb0 = SB + rowL * 80 + c16 * 16;
    const uint32_t smbase = (uint32_t)__cvta_generic_to_shared(smem);
    const uint32_t uaA = smbase + (wm * 64 + (lane & 15)) * 80 + (lane >> 4) * 16;
    const uint32_t uaB = smbase + 20480 +
        (wn * 32 + (lane & 7) + ((lane & 16) ? 8 : 0)) * 80 + ((lane & 8) ? 16 : 0);

    // prefetch chunk 0 (block 0: A hi, W hi)
    {
        *(uint4*)(sa0) = *(const uint4*)(Ag0);
        *(uint4*)(sa0 + 5120) = *(const uint4*)(Ag1);
        *(uint4*)(sb0) = *(const uint4*)(Wg0);
        *(uint4*)(sb0 + 5120) = *(const uint4*)(Wg1);
    }
    __syncthreads();

    for (int c = 0; c < NCH; c++) {
        uint4 av0, av1, wv0, wv1;
        const int nc = c + 1;
        if (nc < NCH) {
            int blk = nc >> 5, kin = (nc & 31) * 32;
            int aoff = kin + ((blk == 2) ? 1024 : 0);
            int woff = kin + ((blk == 1) ? 1024 : 0);
            av0 = *(const uint4*)(Ag0 + aoff);
            av1 = *(const uint4*)(Ag1 + aoff);
            wv0 = *(const uint4*)(Wg0 + woff);
            wv1 = *(const uint4*)(Wg1 + woff);
        }
        const uint32_t stg = (c & 1) * 10240;
#pragma unroll
        for (int ks = 0; ks < 2; ks++) {
            uint32_t af[4][4], bf[2][4];
#pragma unroll
            for (int mt = 0; mt < 4; mt++) ldsm4(af[mt], uaA + stg + mt * 1280 + ks * 32);
#pragma unroll
            for (int p = 0; p < 2; p++) ldsm4(bf[p], uaB + stg + p * 1280 + ks * 32);
#pragma unroll
            for (int mt = 0; mt < 4; mt++)
#pragma unroll
                for (int nt = 0; nt < 4; nt++)
                    mma16816(acc[mt][nt], af[mt], bf[nt >> 1][(nt & 1) * 2],
                             bf[nt >> 1][(nt & 1) * 2 + 1]);
        }
        if (nc < NCH) {
            const int ns = (nc & 1) * 10240;
            *(uint4*)(sa0 + ns) = av0;
            *(uint4*)(sa0 + ns + 5120) = av1;
            *(uint4*)(sb0 + ns) = wv0;
            *(uint4*)(sb0 + ns + 5120) = wv1;
        }
        __syncthreads();
    }

    // epilogue: bias + remap out[b][t+1][n]
#pragma unroll
    for (int nt = 0; nt < 4; nt++) {
        const int n = n0 + wn * 32 + nt * 8 + (lane & 3) * 2;
        const float2 bb = *(const float2*)(bias + n);
#pragma unroll
        for (int mt = 0; mt < 4; mt++) {
#pragma unroll
            for (int half = 0; half < 2; half++) {
                const int m = m0 + wm * 64 + mt * 16 + (lane >> 2) + half * 8;
                if (m < MROWS) {
                    const int t = m >> 5, b = m & 31;
                    float2 v;
                    v.x = acc[mt][nt][half * 2 + 0] + bb.x;
                    v.y = acc[mt][nt][half * 2 + 1] + bb.y;
                    *(float2*)(out + (size_t)(b * T_ + t + 1) * V_ + n) = v;
                }
            }
        }
    }
}

// ---------------- launch ----------------
extern "C" void kernel_launch(void* const* d_in, const int* in_sizes, int n_in,
                              void* d_out, int out_size)
{
    (void)in_sizes; (void)n_in; (void)out_size;
    const int*   src     = (const int*)d_in[0];
    const int*   trg     = (const int*)d_in[1];
    const float* enc_emb = (const float*)d_in[2];
    const float* dec_emb = (const float*)d_in[3];
    const float* eWih_f  = (const float*)d_in[4];
    const float* eWhh_f  = (const float*)d_in[5];
    const float* eb_f    = (const float*)d_in[6];
    const float* eWih_b  = (const float*)d_in[7];
    const float* eWhh_b  = (const float*)d_in[8];
    const float* eb_b    = (const float*)d_in[9];
    const float* dWih    = (const float*)d_in[10];
    const float* dWhh    = (const float*)d_in[11];
    const float* db      = (const float*)d_in[12];
    const float* fcW     = (const float*)d_in[13];
    const float* fcb     = (const float*)d_in[14];
    float* out = (float*)d_out;

    cudaFuncSetAttribute(enc_persist_k, cudaFuncAttributeMaxDynamicSharedMemorySize,
                         H_ * B_ * 4);
    cudaFuncSetAttribute(dec_persist_k, cudaFuncAttributeMaxDynamicSharedMemorySize,
                         DH * B_ * 4);

    void *p_pre_fT, *p_pre_bT, *p_dec_preT, *p_enc_ri, *p_dec_ri;
    cudaGetSymbolAddress(&p_pre_fT, g_pre_fT);
    cudaGetSymbolAddress(&p_pre_bT, g_pre_bT);
    cudaGetSymbolAddress(&p_dec_preT, g_dec_preT);
    cudaGetSymbolAddress(&p_enc_ri, g_enc_rowidx);
    cudaGetSymbolAddress(&p_dec_ri, g_dec_rowidx);

    long total = (long)B_ * V_ + 2L * H_ * B_ + (long)S_ * B_ + (long)TD * B_
               + 256 + (long)(MPAD - MROWS) * 2048;
    prep_k<<<(unsigned)((total + 255) / 256), 256>>>(src, trg, out);
    wconv_k<<<V_, 256>>>(fcW);

    sgemm_k<<<dim3(GH / 128, (S_ * B_) / 128), 256>>>(
        enc_emb, eWih_f, eb_f, (const int*)p_enc_ri, (float*)p_pre_fT, S_ * B_, GH, E_);
    sgemm_k<<<dim3(GH / 128, (S_ * B_) / 128), 256>>>(
        enc_emb, eWih_b, eb_b, (const int*)p_enc_ri, (float*)p_pre_bT, S_ * B_, GH, E_);
    sgemm_k<<<dim3(DG / 128, (TD * B_ + 127) / 128), 256>>>(
        dec_emb, dWih, db, (const int*)p_dec_ri, (float*)p_dec_preT, TD * B_, DG, E_);

    enc_persist_k<<<128, 256, H_ * B_ * 4>>>(eWhh_f, eWhh_b);
    dec_persist_k<<<128, 256, DH * B_ * 4>>>(dWhh);

    bgemm_k<<<dim3(V_ / 128, MPAD / 128), 256>>>(fcb, out);
}

// round 6
// speedup vs baseline: 1.0784x; 1.0031x over previous
#include <cuda_runtime.h>
#include <cuda_bf16.h>
#include <math.h>
#include <stdint.h>

#define B_  32
#define S_  128
#define T_  64
#define E_  256
#define H_  512
#define V_  32000
#define GH  2048
#define DH  1024
#define DG  4096
#define TD  63
#define MROWS 2016
#define MPAD  2048

// Feature gate: tcgen05 is only legal in the compute_103a/compute_100a pass.
// Host pass (no __CUDA_ARCH__) keeps HAS_TC=1 so kernel signatures exist.
#if defined(__CUDA_ARCH_FEAT_SM103_ALL) || defined(__CUDA_ARCH_FEAT_SM100_ALL) || !defined(__CUDA_ARCH__)
#define HAS_TC 1
#else
#define HAS_TC 0
#endif

// ---------------- scratch ----------------
__device__ float g_pre_fT[(size_t)S_ * GH * B_];
__device__ float g_pre_bT[(size_t)S_ * GH * B_];
__device__ float g_dec_preT[(size_t)TD * DG * B_];
__device__ float g_enc_hT[2][2][H_ * B_];
__device__ float g_enc_cT[2][H_ * B_];
__device__ float g_dec_hT[2][DH * B_];
__device__ int   g_enc_rowidx[S_ * B_];
__device__ int   g_dec_rowidx[TD * B_];
__device__ __nv_bfloat16 g_Abig[(size_t)MPAD * 2048];   // [hi(1024) | lo(1024)]
__device__ __nv_bfloat16 g_Wbig[(size_t)V_ * 2048];     // [hi | lo]
__device__ unsigned g_flagsA[128];
__device__ unsigned g_flagsB[128];
__device__ int g_has_tc;

// ---------------- grid barrier ----------------
__device__ __forceinline__ void grid_barrier(unsigned* flags, unsigned target)
{
    __threadfence();
    __syncthreads();
    if (threadIdx.x == 0)
        asm volatile("st.release.gpu.u32 [%0], %1;" :: "l"(flags + blockIdx.x),
                     "r"(target) : "memory");
    if (threadIdx.x < 128) {
        unsigned v;
        do {
            asm volatile("ld.acquire.gpu.u32 %0, [%1];" : "=r"(v)
                         : "l"(flags + threadIdx.x) : "memory");
        } while (v < target);
    }
    __syncthreads();
}

// ---------------- prep ----------------
__global__ void prep_k(const int* __restrict__ src, const int* __restrict__ trg,
                       float* __restrict__ out)
{
    if (blockIdx.x == 0 && threadIdx.x == 0) {
#if HAS_TC
        g_has_tc = 1;
#else
        g_has_tc = 0;
#endif
    }
    long idx = (long)blockIdx.x * blockDim.x + threadIdx.x;
    const long N0 = (long)B_ * V_;
    if (idx < N0) {
        long b = idx / V_, v = idx - b * V_;
        out[(size_t)b * T_ * V_ + v] = 0.f;
        return;
    }
    idx -= N0;
    if (idx < 2 * H_ * B_) { g_enc_hT[idx >> 14][0][idx & 16383] = 0.f; return; }
    idx -= 2 * H_ * B_;
    if (idx < S_ * B_) {
        int t = (int)(idx / B_), b = (int)(idx % B_);
        g_enc_rowidx[idx] = src[b * S_ + t];
        return;
    }
    idx -= S_ * B_;
    if (idx < TD * B_) {
        int t = (int)(idx / B_), b = (int)(idx % B_);
        g_dec_rowidx[idx] = trg[b * T_ + t];
        return;
    }
    idx -= TD * B_;
    if (idx < 128) { g_flagsA[idx] = 0; return; }
    idx -= 128;
    if (idx < 128) { g_flagsB[idx] = 0; return; }
    idx -= 128;
    if (idx < (MPAD - MROWS) * 2048) {   // zero A pad rows
        g_Abig[(size_t)(MROWS + (idx >> 11)) * 2048 + (idx & 2047)] = __float2bfloat16(0.f);
        return;
    }
}

// ---------------- W split conversion ----------------
__global__ void wconv_k(const float* __restrict__ fcW)
{
    size_t i = (size_t)blockIdx.x * 256 + threadIdx.x;
    if (i >= (size_t)V_ * 256) return;
    size_t n = i >> 8; int k4 = (int)(i & 255);
    float4 v = __ldcg((const float4*)fcW + i);
    __nv_bfloat16 h0 = __float2bfloat16(v.x), h1 = __float2bfloat16(v.y);
    __nv_bfloat16 h2 = __float2bfloat16(v.z), h3 = __float2bfloat16(v.w);
    __nv_bfloat16 l0 = __float2bfloat16(v.x - __bfloat162float(h0));
    __nv_bfloat16 l1 = __float2bfloat16(v.y - __bfloat162float(h1));
    __nv_bfloat16 l2 = __float2bfloat16(v.z - __bfloat162float(h2));
    __nv_bfloat16 l3 = __float2bfloat16(v.w - __bfloat162float(h3));
    __nv_bfloat162* dh = (__nv_bfloat162*)(g_Wbig + n * 2048 + k4 * 4);
    __nv_bfloat162* dl = (__nv_bfloat162*)(g_Wbig + n * 2048 + 1024 + k4 * 4);
    __nv_bfloat162 a; a.x = h0; a.y = h1; dh[0] = a;
    __nv_bfloat162 b; b.x = h2; b.y = h3; dh[1] = b;
    __nv_bfloat162 c; c.x = l0; c.y = l1; dl[0] = c;
    __nv_bfloat162 d; d.x = l2; d.y = l3; dl[1] = d;
}

// ---------------- pregate SGEMM (transposed output [t][gate][b]) ----------------
__global__ void sgemm_k(const float* __restrict__ A, const float* __restrict__ W,
                        const float* __restrict__ bias, const int* __restrict__ rowidx,
                        float* __restrict__ C, int M, int N, int K)
{
    __shared__ float As[16][128];
    __shared__ float Bs[16][128];
    const int tid = threadIdx.x;
    const int m0 = blockIdx.y * 128, n0 = blockIdx.x * 128;
    const int lm = tid & 127, lq = tid >> 7;
    int mm = m0 + lm; if (mm >= M) mm = M - 1;
    const float* aptr = A + (size_t)rowidx[mm] * K;
    const float* bptr = W + (size_t)(n0 + lm) * K;
    const int tx = tid & 15, ty = tid >> 4;
    float acc[8][8];
#pragma unroll
    for (int i = 0; i < 8; i++)
#pragma unroll
        for (int j = 0; j < 8; j++) acc[i][j] = 0.f;

    for (int k0 = 0; k0 < K; k0 += 16) {
        float4 a0 = *(const float4*)(aptr + k0 + 4 * lq);
        float4 a1 = *(const float4*)(aptr + k0 + 4 * lq + 8);
        float4 b0 = *(const float4*)(bptr + k0 + 4 * lq);
        float4 b1 = *(const float4*)(bptr + k0 + 4 * lq + 8);
        __syncthreads();
        As[4 * lq + 0][lm] = a0.x; As[4 * lq + 1][lm] = a0.y;
        As[4 * lq + 2][lm] = a0.z; As[4 * lq + 3][lm] = a0.w;
        As[4 * lq + 8][lm] = a1.x; As[4 * lq + 9][lm] = a1.y;
        As[4 * lq + 10][lm] = a1.z; As[4 * lq + 11][lm] = a1.w;
        Bs[4 * lq + 0][lm] = b0.x; Bs[4 * lq + 1][lm] = b0.y;
        Bs[4 * lq + 2][lm] = b0.z; Bs[4 * lq + 3][lm] = b0.w;
        Bs[4 * lq + 8][lm] = b1.x; Bs[4 * lq + 9][lm] = b1.y;
        Bs[4 * lq + 10][lm] = b1.z; Bs[4 * lq + 11][lm] = b1.w;
        __syncthreads();
#pragma unroll
        for (int k = 0; k < 16; k++) {
            float ar[8], br[8];
            *(float4*)&ar[0] = *(const float4*)&As[k][ty * 8];
            *(float4*)&ar[4] = *(const float4*)&As[k][ty * 8 + 4];
            *(float4*)&br[0] = *(const float4*)&Bs[k][tx * 8];
            *(float4*)&br[4] = *(const float4*)&Bs[k][tx * 8 + 4];
#pragma unroll
            for (int i = 0; i < 8; i++)
#pragma unroll
                for (int j = 0; j < 8; j++) acc[i][j] += ar[i] * br[j];
        }
    }
#pragma unroll
    for (int i = 0; i < 8; i++) {
        int m = m0 + ty * 8 + i;
        if (m >= M) break;
        int t = m >> 5, b = m & 31;
        const float* bp = bias + n0 + tx * 8;
#pragma unroll
        for (int j = 0; j < 8; j++)
            C[((size_t)t * N + (n0 + tx * 8 + j)) * B_ + b] = acc[i][j] + bp[j];
    }
}

// ---------------- persistent encoder ----------------
__global__ void enc_persist_k(const float* __restrict__ Whh_f,
                              const float* __restrict__ Whh_b)
{
    extern __shared__ float shT[];
    const int dir = blockIdx.x >> 6, cb = blockIdx.x & 63;
    const int w = threadIdx.x >> 5, lane = threadIdx.x & 31;
    const int j = cb * 8 + w;
    const float* Whh = dir ? Whh_b : Whh_f;
    const float* preBase = dir ? g_pre_bT : g_pre_fT;
    const float4* wi = (const float4*)(Whh + (size_t)j * H_);
    const float4* wf = (const float4*)(Whh + (size_t)(H_ + j) * H_);
    const float4* wg = (const float4*)(Whh + (size_t)(2 * H_ + j) * H_);
    const float4* wo = (const float4*)(Whh + (size_t)(3 * H_ + j) * H_);
    float cst = 0.f;

    for (int s = 0; s < S_; s++) {
        const float4* s4 = (const float4*)g_enc_hT[dir][s & 1];
        float4* d4 = (float4*)shT;
        for (int i = threadIdx.x; i < H_ * B_ / 4; i += 256) d4[i] = __ldcg(s4 + i);
        __syncthreads();
        const int t = dir ? (S_ - 1 - s) : s;
        const float* preT = preBase + (size_t)t * GH * B_;
        float ai = __ldcg(preT + (size_t)(0 * H_ + j) * B_ + lane);
        float af = __ldcg(preT + (size_t)(1 * H_ + j) * B_ + lane);
        float ag = __ldcg(preT + (size_t)(2 * H_ + j) * B_ + lane);
        float ao = __ldcg(preT + (size_t)(3 * H_ + j) * B_ + lane);
#pragma unroll 4
        for (int k4 = 0; k4 < H_ / 4; k4++) {
            float4 a = wi[k4], f = wf[k4], g = wg[k4], o = wo[k4];
            float h0 = shT[(k4 * 4 + 0) * B_ + lane];
            float h1 = shT[(k4 * 4 + 1) * B_ + lane];
            float h2 = shT[(k4 * 4 + 2) * B_ + lane];
            float h3 = shT[(k4 * 4 + 3) * B_ + lane];
            ai += h0 * a.x + h1 * a.y + h2 * a.z + h3 * a.w;
            af += h0 * f.x + h1 * f.y + h2 * f.z + h3 * f.w;
            ag += h0 * g.x + h1 * g.y + h2 * g.z + h3 * g.w;
            ao += h0 * o.x + h1 * o.y + h2 * o.z + h3 * o.w;
        }
        float iv = 1.f / (1.f + expf(-ai));
        float fv = 1.f / (1.f + expf(-af));
        float gv = tanhf(ag);
        float ov = 1.f / (1.f + expf(-ao));
        cst = fv * cst + iv * gv;
        g_enc_hT[dir][(s + 1) & 1][(size_t)j * B_ + lane] = ov * tanhf(cst);
        if (s == S_ - 1) g_enc_cT[dir][(size_t)j * B_ + lane] = cst;
        grid_barrier(g_flagsA, s + 1);
    }
}

// ---------------- persistent decoder ----------------
__global__ void dec_persist_k(const float* __restrict__ Whh)
{
    extern __shared__ float shT[];
    const int w = threadIdx.x >> 5, lane = threadIdx.x & 31;
    const int j = blockIdx.x * 8 + w;
    float cst, h0v;
    if (j < H_) { cst = g_enc_cT[0][j * B_ + lane]; h0v = g_enc_hT[0][0][j * B_ + lane]; }
    else { cst = g_enc_cT[1][(j - H_) * B_ + lane]; h0v = g_enc_hT[1][0][(j - H_) * B_ + lane]; }
    g_dec_hT[0][(size_t)j * B_ + lane] = h0v;
    grid_barrier(g_flagsB, 1);

    const float4* wi = (const float4*)(Whh + (size_t)j * DH);
    const float4* wf = (const float4*)(Whh + (size_t)(DH + j) * DH);
    const float4* wg = (const float4*)(Whh + (size_t)(2 * DH + j) * DH);
    const float4* wo = (const float4*)(Whh + (size_t)(3 * DH + j) * DH);

    for (int t = 0; t < TD; t++) {
        const float4* s4 = (const float4*)g_dec_hT[t & 1];
        float4* d4 = (float4*)shT;
        for (int i = threadIdx.x; i < DH * B_ / 4; i += 256) d4[i] = __ldcg(s4 + i);
        __syncthreads();
        const float* preT = g_dec_preT + (size_t)t * DG * B_;
        float ai = __ldcg(preT + (size_t)(0 * DH + j) * B_ + lane);
        float af = __ldcg(preT + (size_t)(1 * DH + j) * B_ + lane);
        float ag = __ldcg(preT + (size_t)(2 * DH + j) * B_ + lane);
        float ao = __ldcg(preT + (size_t)(3 * DH + j) * B_ + lane);
#pragma unroll 4
        for (int k4 = 0; k4 < DH / 4; k4++) {
            float4 a = wi[k4], f = wf[k4], g = wg[k4], o = wo[k4];
            float h0 = shT[(k4 * 4 + 0) * B_ + lane];
            float h1 = shT[(k4 * 4 + 1) * B_ + lane];
            float h2 = shT[(k4 * 4 + 2) * B_ + lane];
            float h3 = shT[(k4 * 4 + 3) * B_ + lane];
            ai += h0 * a.x + h1 * a.y + h2 * a.z + h3 * a.w;
            af += h0 * f.x + h1 * f.y + h2 * f.z + h3 * f.w;
            ag += h0 * g.x + h1 * g.y + h2 * g.z + h3 * g.w;
            ao += h0 * o.x + h1 * o.y + h2 * o.z + h3 * o.w;
        }
        float iv = 1.f / (1.f + expf(-ai));
        float fv = 1.f / (1.f + expf(-af));
        float gv = tanhf(ag);
        float ov = 1.f / (1.f + expf(-ao));
        cst = fv * cst + iv * gv;
        float hv = ov * tanhf(cst);
        g_dec_hT[(t + 1) & 1][(size_t)j * B_ + lane] = hv;
        size_t m = (size_t)t * B_ + lane;
        __nv_bfloat16 hi = __float2bfloat16(hv);
        g_Abig[m * 2048 + j] = hi;
        g_Abig[m * 2048 + 1024 + j] = __float2bfloat16(hv - __bfloat162float(hi));
        grid_barrier(g_flagsB, t + 2);
    }
}

// ================= tcgen05 final GEMM =================
#define KCH    16
#define STAGE  98304
#define OFF_AHI0 0
#define OFF_AHI1 16384
#define OFF_ALO0 32768
#define OFF_ALO1 49152
#define OFF_WHI  65536
#define OFF_WLO  81920
#define SMEM_HDR 1024
#define SMEM_TC  (SMEM_HDR + 2 * STAGE)
#define IDESC_F16 ((1u<<4)|(1u<<7)|(1u<<10)|((128u/8)<<17)|((128u/16)<<24))

static __device__ __forceinline__ uint32_t swz(uint32_t x) { return x ^ ((x >> 3) & 0x70); }

__device__ __forceinline__ uint32_t smem_u32(const void* p)
{
    uint32_t a;
    asm("{ .reg .u64 t; cvta.to.shared.u64 t, %1; cvt.u32.u64 %0, t; }" : "=r"(a) : "l"(p));
    return a;
}
__device__ __forceinline__ void cp16(uint32_t dst, const void* src)
{
    asm volatile("cp.async.cg.shared.global [%0], [%1], 16;" :: "r"(dst), "l"(src));
}

#if HAS_TC
__device__ __forceinline__ uint32_t elect1()
{
    uint32_t p;
    asm volatile("{ .reg .pred p; elect.sync _|p, 0xFFFFFFFF; selp.b32 %0, 1, 0, p; }" : "=r"(p));
    return p;
}
__device__ __forceinline__ void mma_f16_ss(uint32_t d, uint64_t ad, uint64_t bd,
                                           uint32_t idesc, uint32_t en)
{
    asm volatile(
        "{\n\t.reg .pred p;\n\tsetp.ne.u32 p, %5, 0;\n\t"
        "tcgen05.mma.cta_group::1.kind::f16 [%0], %1, %2, %3, {%4,%4,%4,%4}, p;\n\t}"
        :: "r"(d), "l"(ad), "l"(bd), "r"(idesc), "r"(0u), "r"(en) : "memory");
}
#endif

__device__ __forceinline__ void load_chunk(const __nv_bfloat16* Ag, const __nv_bfloat16* Wg,
                                           int kc, uint32_t sbase, int tid)
{
    {
        const __nv_bfloat16* sA = Ag + (size_t)tid * 2048 + kc;
        uint32_t abase = sbase + ((tid < 128) ? OFF_AHI0 : OFF_AHI1);
        uint32_t lbase = sbase + ((tid < 128) ? OFF_ALO0 : OFF_ALO1);
        uint32_t r = (tid & 127) * 128;
#pragma unroll
        for (int g = 0; g < 8; g++) cp16(abase + swz(r + g * 16), sA + g * 8);
#pragma unroll
        for (int g = 0; g < 8; g++) cp16(lbase + swz(r + g * 16), sA + 1024 + g * 8);
    }
    {
        int rw = tid >> 1, g0 = (tid & 1) * 4;
        const __nv_bfloat16* sW = Wg + (size_t)rw * 2048 + kc + g0 * 8;
        uint32_t r = rw * 128 + g0 * 16;
#pragma unroll
        for (int g = 0; g < 4; g++) cp16(sbase + OFF_WHI + swz(r + g * 16), sW + g * 8);
#pragma unroll
        for (int g = 0; g < 4; g++) cp16(sbase + OFF_WLO + swz(r + g * 16), sW + 1024 + g * 8);
    }
    asm volatile("cp.async.commit_group;" ::: "memory");
}

__global__ __launch_bounds__(256, 1)
void bgemm_tc(const float* __restrict__ bias, float* __restrict__ out)
{
#if HAS_TC
    extern __shared__ __align__(1024) unsigned char sm[];
    const uint32_t sbase = smem_u32(sm);
    const int tid = threadIdx.x, wid = tid >> 5, lane = tid & 31;
    const int n0 = blockIdx.x * 128;
    const int m0g = blockIdx.y * 256;
    const __nv_bfloat16* Ag = g_Abig + (size_t)m0g * 2048;
    const __nv_bfloat16* Wg = g_Wbig + (size_t)n0 * 2048;

    if (wid == 0)
        asm volatile("tcgen05.alloc.cta_group::1.sync.aligned.shared::cta.b32 [%0], 512;"
                     :: "r"(sbase) : "memory");
    if (tid == 0) {
        asm volatile("mbarrier.init.shared.b64 [%0], 1;" :: "r"(sbase + 16) : "memory");
        asm volatile("mbarrier.init.shared.b64 [%0], 1;" :: "r"(sbase + 24) : "memory");
    }
    __syncthreads();
    uint32_t tmem;
    asm volatile("ld.shared.b32 %0, [%1];" : "=r"(tmem) : "r"(sbase));

    load_chunk(Ag, Wg, 0, sbase + SMEM_HDR, tid);
    load_chunk(Ag, Wg, 64, sbase + SMEM_HDR + STAGE, tid);

    int phase0 = 0, phase1 = 0;
    for (int c = 0; c < KCH; c++) {
        const int p = c & 1;
        if (c + 1 < KCH) asm volatile("cp.async.wait_group 1;" ::: "memory");
        else             asm volatile("cp.async.wait_group 0;" ::: "memory");
        __syncthreads();
        asm volatile("fence.proxy.async.shared::cta;" ::: "memory");

        if (wid == 0 && elect1()) {
            const uint32_t st = sbase + SMEM_HDR + p * STAGE;
            const uint64_t BASE = (uint64_t(2) << 61) | (uint64_t(1) << 46) |
                                  (uint64_t(64) << 32) | (uint64_t(1) << 16);
            uint64_t dAhi0 = BASE | (((st + OFF_AHI0) >> 4) & 0x3FFF);
            uint64_t dAhi1 = BASE | (((st + OFF_AHI1) >> 4) & 0x3FFF);
            uint64_t dAlo0 = BASE | (((st + OFF_ALO0) >> 4) & 0x3FFF);
            uint64_t dAlo1 = BASE | (((st + OFF_ALO1) >> 4) & 0x3FFF);
            uint64_t dWhi  = BASE | (((st + OFF_WHI) >> 4) & 0x3FFF);
            uint64_t dWlo  = BASE | (((st + OFF_WLO) >> 4) & 0x3FFF);
#pragma unroll
            for (int ks = 0; ks < 4; ks++) {
                uint32_t en0 = (c == 0 && ks == 0) ? 0u : 1u;
                mma_f16_ss(tmem + 0,   dAhi0 + ks * 2, dWhi + ks * 2, IDESC_F16, en0);
                mma_f16_ss(tmem + 128, dAhi1 + ks * 2, dWhi + ks * 2, IDESC_F16, en0);
                mma_f16_ss(tmem + 0,   dAhi0 + ks * 2, dWlo + ks * 2, IDESC_F16, 1u);
                mma_f16_ss(tmem + 128, dAhi1 + ks * 2, dWlo + ks * 2, IDESC_F16, 1u);
                mma_f16_ss(tmem + 0,   dAlo0 + ks * 2, dWhi + ks * 2, IDESC_F16, 1u);
                mma_f16_ss(tmem + 128, dAlo1 + ks * 2, dWhi + ks * 2, IDESC_F16, 1u);
            }
            asm volatile(
                "tcgen05.commit.cta_group::1.mbarrier::arrive::one.shared::cluster.b64 [%0];"
                :: "r"(sbase + 16 + p * 8) : "memory");
        }
        {
            uint32_t mb = sbase + 16 + p * 8;
            uint32_t ph = p ? phase1 : phase0;
            uint32_t done;
            asm volatile(
                "{\n\t.reg .pred q;\n\t"
                "mbarrier.try_wait.parity.shared.b64 q, [%1], %2, 0x989680;\n\t"
                "selp.b32 %0, 1, 0, q;\n\t}"
                : "=r"(done) : "r"(mb), "r"(ph) : "memory");
            while (!done) {
                asm volatile(
                    "{\n\t.reg .pred q;\n\t"
                    "mbarrier.try_wait.parity.shared.b64 q, [%1], %2, 0x989680;\n\t"
                    "selp.b32 %0, 1, 0, q;\n\t}"
                    : "=r"(done) : "r"(mb), "r"(ph) : "memory");
            }
            if (p) phase1 ^= 1; else phase0 ^= 1;
        }
        if (c + 2 < KCH)
            load_chunk(Ag, Wg, (c + 2) * 64, sbase + SMEM_HDR + p * STAGE, tid);
    }

    asm volatile("tcgen05.fence::after_thread_sync;" ::: "memory");
    {
        const int sub = tid >> 7;
        const int wiw = (tid >> 5) & 3;
        const int mrow = m0g + sub * 128 + wiw * 32 + lane;
        const uint32_t warp_off = ((uint32_t)(tid & 127) >> 5) << 21;
        const uint32_t dbase = tmem + sub * 128 + warp_off;
        if (mrow < MROWS) {
            const int t = mrow >> 5, b = mrow & 31;
            float* orow = out + (size_t)(b * T_ + t + 1) * V_ + n0;
#pragma unroll
            for (int q = 0; q < 4; q++) {
                uint32_t r[32];
                asm volatile(
                    "tcgen05.ld.sync.aligned.32x32b.x32.b32 "
                    "{%0,%1,%2,%3,%4,%5,%6,%7,%8,%9,%10,%11,%12,%13,%14,%15,"
                    "%16,%17,%18,%19,%20,%21,%22,%23,%24,%25,%26,%27,%28,%29,%30,%31}, [%32];"
                    : "=r"(r[0]), "=r"(r[1]), "=r"(r[2]), "=r"(r[3]), "=r"(r[4]), "=r"(r[5]),
                      "=r"(r[6]), "=r"(r[7]), "=r"(r[8]), "=r"(r[9]), "=r"(r[10]), "=r"(r[11]),
                      "=r"(r[12]), "=r"(r[13]), "=r"(r[14]), "=r"(r[15]), "=r"(r[16]), "=r"(r[17]),
                      "=r"(r[18]), "=r"(r[19]), "=r"(r[20]), "=r"(r[21]), "=r"(r[22]), "=r"(r[23]),
                      "=r"(r[24]), "=r"(r[25]), "=r"(r[26]), "=r"(r[27]), "=r"(r[28]), "=r"(r[29]),
                      "=r"(r[30]), "=r"(r[31])
                    : "r"(dbase + q * 32));
                asm volatile("tcgen05.wait::ld.sync.aligned;" ::: "memory");
#pragma unroll
                for (int c4 = 0; c4 < 8; c4++) {
                    const int n = q * 32 + c4 * 4;
                    float4 bb = *(const float4*)(bias + n0 + n);
                    float4 v;
                    v.x = __uint_as_float(r[c4 * 4 + 0]) + bb.x;
                    v.y = __uint_as_float(r[c4 * 4 + 1]) + bb.y;
                    v.z = __uint_as_float(r[c4 * 4 + 2]) + bb.z;
                    v.w = __uint_as_float(r[c4 * 4 + 3]) + bb.w;
                    *(float4*)(orow + n) = v;
                }
            }
        } else {
#pragma unroll
            for (int q = 0; q < 4; q++) {
                uint32_t r0;
                asm volatile("tcgen05.ld.sync.aligned.32x32b.x1.b32 {%0}, [%1];"
                             : "=r"(r0) : "r"(dbase + q * 32));
                asm volatile("tcgen05.wait::ld.sync.aligned;" ::: "memory");
            }
        }
    }
    __syncthreads();
    if (wid == 0) {
        asm volatile("tcgen05.relinquish_alloc_permit.cta_group::1.sync.aligned;" ::: "memory");
        asm volatile("tcgen05.dealloc.cta_group::1.sync.aligned.b32 %0, 512;" :: "r"(tmem));
    }
#endif  // HAS_TC
}

// ---------------- mma.sync fallback GEMM (runs only if tcgen05 pass absent) ----------------
__device__ __forceinline__ void ldsm4(uint32_t* r, uint32_t addr)
{
    asm volatile("ldmatrix.sync.aligned.m8n8.x4.shared.b16 {%0,%1,%2,%3}, [%4];"
                 : "=r"(r[0]), "=r"(r[1]), "=r"(r[2]), "=r"(r[3]) : "r"(addr));
}
__device__ __forceinline__ void mma16816(float* d, const uint32_t* a, uint32_t b0, uint32_t b1)
{
    asm volatile("mma.sync.aligned.m16n8k16.row.col.f32.bf16.bf16.f32 "
                 "{%0,%1,%2,%3},{%4,%5,%6,%7},{%8,%9},{%0,%1,%2,%3};"
                 : "+f"(d[0]), "+f"(d[1]), "+f"(d[2]), "+f"(d[3])
                 : "r"(a[0]), "r"(a[1]), "r"(a[2]), "r"(a[3]), "r"(b0), "r"(b1));
}

__global__ __launch_bounds__(256, 2)
void bgemm_mma(const float* __restrict__ bias, float* __restrict__ out)
{
    if (g_has_tc) return;
    __shared__ __align__(16) unsigned char smem[40960];
    const int tid = threadIdx.x, lane = tid & 31, w = tid >> 5;
    const int wm = w >> 2, wn = w & 3;
    const int n0 = blockIdx.x * 128, m0 = blockIdx.y * 128;

    float acc[4][4][4];
#pragma unroll
    for (int a = 0; a < 4; a++)
#pragma unroll
        for (int b = 0; b < 4; b++)
#pragma unroll
            for (int c = 0; c < 4; c++) acc[a][b][c] = 0.f;

    const int rowL = tid >> 2, c16 = tid & 3;
    const __nv_bfloat16* Ag0 = g_Abig + (size_t)(m0 + rowL) * 2048 + c16 * 8;
    const __nv_bfloat16* Ag1 = Ag0 + (size_t)64 * 2048;
    const __nv_bfloat16* Wg0 = g_Wbig + (size_t)(n0 + rowL) * 2048 + c16 * 8;
    const __nv_bfloat16* Wg1 = Wg0 + (size_t)64 * 2048;
    unsigned char* SA = smem;
    unsigned char* SB = smem + 20480;
    unsigned char* sa0 = SA + rowL * 80 + c16 * 16;
    unsigned char* sb0 = SB + rowL * 80 + c16 * 16;
    const uint32_t smbase = (uint32_t)__cvta_generic_to_shared(smem);
    const uint32_t uaA = smbase + (wm * 64 + (lane & 15)) * 80 + (lane >> 4) * 16;
    const uint32_t uaB = smbase + 20480 +
        (wn * 32 + (lane & 7) + ((lane & 16) ? 8 : 0)) * 80 + ((lane & 8) ? 16 : 0);

    {
        *(uint4*)(sa0) = *(const uint4*)(Ag0);
        *(uint4*)(sa0 + 5120) = *(const uint4*)(Ag1);
        *(uint4*)(sb0) = *(const uint4*)(Wg0);
        *(uint4*)(sb0 + 5120) = *(const uint4*)(Wg1);
    }
    __syncthreads();

    for (int c = 0; c < 96; c++) {
        uint4 av0, av1, wv0, wv1;
        const int nc = c + 1;
        if (nc < 96) {
            int blk = nc >> 5, kin = (nc & 31) * 32;
            int aoff = kin + ((blk == 2) ? 1024 : 0);
            int woff = kin + ((blk == 1) ? 1024 : 0);
            av0 = *(const uint4*)(Ag0 + aoff);
            av1 = *(const uint4*)(Ag1 + aoff);
            wv0 = *(const uint4*)(Wg0 + woff);
            wv1 = *(const uint4*)(Wg1 + woff);
        }
        const uint32_t stg = (c & 1) * 10240;
#pragma unroll
        for (int ks = 0; ks < 2; ks++) {
            uint32_t af[4][4], bf[2][4];
#pragma unroll
            for (int mt = 0; mt < 4; mt++) ldsm4(af[mt], uaA + stg + mt * 1280 + ks * 32);
#pragma unroll
            for (int p = 0; p < 2; p++) ldsm4(bf[p], uaB + stg + p * 1280 + ks * 32);
#pragma unroll
            for (int mt = 0; mt < 4; mt++)
#pragma unroll
                for (int nt = 0; nt < 4; nt++)
                    mma16816(acc[mt][nt], af[mt], bf[nt >> 1][(nt & 1) * 2],
                             bf[nt >> 1][(nt & 1) * 2 + 1]);
        }
        if (nc < 96) {
            const int ns = (nc & 1) * 10240;
            *(uint4*)(sa0 + ns) = av0;
            *(uint4*)(sa0 + ns + 5120) = av1;
            *(uint4*)(sb0 + ns) = wv0;
            *(uint4*)(sb0 + ns + 5120) = wv1;
        }
        __syncthreads();
    }

#pragma unroll
    for (int nt = 0; nt < 4; nt++) {
        const int n = n0 + wn * 32 + nt * 8 + (lane & 3) * 2;
        const float2 bb = *(const float2*)(bias + n);
#pragma unroll
        for (int mt = 0; mt < 4; mt++) {
#pragma unroll
            for (int half = 0; half < 2; half++) {
                const int m = m0 + wm * 64 + mt * 16 + (lane >> 2) + half * 8;
                if (m < MROWS) {
                    const int t = m >> 5, b = m & 31;
                    float2 v;
                    v.x = acc[mt][nt][half * 2 + 0] + bb.x;
                    v.y = acc[mt][nt][half * 2 + 1] + bb.y;
                    *(float2*)(out + (size_t)(b * T_ + t + 1) * V_ + n) = v;
                }
            }
        }
    }
}

// ---------------- launch ----------------
extern "C" void kernel_launch(void* const* d_in, const int* in_sizes, int n_in,
                              void* d_out, int out_size)
{
    (void)in_sizes; (void)n_in; (void)out_size;
    const int*   src     = (const int*)d_in[0];
    const int*   trg     = (const int*)d_in[1];
    const float* enc_emb = (const float*)d_in[2];
    const float* dec_emb = (const float*)d_in[3];
    const float* eWih_f  = (const float*)d_in[4];
    const float* eWhh_f  = (const float*)d_in[5];
    const float* eb_f    = (const float*)d_in[6];
    const float* eWih_b  = (const float*)d_in[7];
    const float* eWhh_b  = (const float*)d_in[8];
    const float* eb_b    = (const float*)d_in[9];
    const float* dWih    = (const float*)d_in[10];
    const float* dWhh    = (const float*)d_in[11];
    const float* db      = (const float*)d_in[12];
    const float* fcW     = (const float*)d_in[13];
    const float* fcb     = (const float*)d_in[14];
    float* out = (float*)d_out;

    cudaFuncSetAttribute(enc_persist_k, cudaFuncAttributeMaxDynamicSharedMemorySize,
                         H_ * B_ * 4);
    cudaFuncSetAttribute(dec_persist_k, cudaFuncAttributeMaxDynamicSharedMemorySize,
                         DH * B_ * 4);
    cudaFuncSetAttribute(bgemm_tc, cudaFuncAttributeMaxDynamicSharedMemorySize, SMEM_TC);

    void *p_pre_fT, *p_pre_bT, *p_dec_preT, *p_enc_ri, *p_dec_ri;
    cudaGetSymbolAddress(&p_pre_fT, g_pre_fT);
    cudaGetSymbolAddress(&p_pre_bT, g_pre_bT);
    cudaGetSymbolAddress(&p_dec_preT, g_dec_preT);
    cudaGetSymbolAddress(&p_enc_ri, g_enc_rowidx);
    cudaGetSymbolAddress(&p_dec_ri, g_dec_rowidx);

    long total = (long)B_ * V_ + 2L * H_ * B_ + (long)S_ * B_ + (long)TD * B_
               + 256 + (long)(MPAD - MROWS) * 2048;
    prep_k<<<(unsigned)((total + 255) / 256), 256>>>(src, trg, out);
    wconv_k<<<V_, 256>>>(fcW);

    sgemm_k<<<dim3(GH / 128, (S_ * B_) / 128), 256>>>(
        enc_emb, eWih_f, eb_f, (const int*)p_enc_ri, (float*)p_pre_fT, S_ * B_, GH, E_);
    sgemm_k<<<dim3(GH / 128, (S_ * B_) / 128), 256>>>(
        enc_emb, eWih_b, eb_b, (const int*)p_enc_ri, (float*)p_pre_bT, S_ * B_, GH, E_);
    sgemm_k<<<dim3(DG / 128, (TD * B_ + 127) / 128), 256>>>(
        dec_emb, dWih, db, (const int*)p_dec_ri, (float*)p_dec_preT, TD * B_, DG, E_);

    enc_persist_k<<<128, 256, H_ * B_ * 4>>>(eWhh_f, eWhh_b);
    dec_persist_k<<<128, 256, DH * B_ * 4>>>(dWhh);

    bgemm_tc<<<dim3(V_ / 128, MPAD / 256), 256, SMEM_TC>>>(fcb, out);
    bgemm_mma<<<dim3(V_ / 128, MPAD / 128), 256>>>(fcb, out);
}

// round 7
// speedup vs baseline: 1.2411x; 1.1509x over previous
#include <cuda_runtime.h>
#include <cuda_bf16.h>
#include <math.h>
#include <stdint.h>

#define B_  32
#define S_  128
#define T_  64
#define E_  256
#define H_  512
#define V_  32000
#define GH  2048
#define DH  1024
#define DG  4096
#define TD  63
#define MROWS 2016
#define MPAD  2048

// tcgen05 only legal in the compute_103a feature pass.
#if defined(__CUDA_ARCH_FEAT_SM103_ALL) || defined(__CUDA_ARCH_FEAT_SM100_ALL) || !defined(__CUDA_ARCH__)
#define HAS_TC 1
#else
#define HAS_TC 0
#endif

// ---------------- scratch ----------------
__device__ float g_pre_fT[(size_t)S_ * GH * B_];
__device__ float g_pre_bT[(size_t)S_ * GH * B_];
__device__ float g_dec_preT[(size_t)TD * DG * B_];
__device__ float g_enc_hT[2][2][H_ * B_];
__device__ float g_enc_cT[2][H_ * B_];
__device__ float g_dec_hT[2][DH * B_];
__device__ int   g_enc_rowidx[S_ * B_];
__device__ int   g_dec_rowidx[TD * B_];
__device__ __nv_bfloat16 g_Abig[(size_t)MPAD * 2048];   // [hi(1024) | lo(1024)]
__device__ __nv_bfloat16 g_Wbig[(size_t)V_ * 2048];     // [hi | lo]
// sync cells, 128B apart: [0]=cnt_enc0 [32]=gen_enc0 [64]=cnt_enc1 [96]=gen_enc1
// [128]=cnt_dec [160]=gen_dec
__device__ unsigned g_sync[192];
__device__ int g_has_tc;

// ---------------- grid barrier: 1 arrive RMW + 1 poller per block ----------------
__device__ __forceinline__ void grid_barrier2(unsigned* cnt, unsigned* gen,
                                              unsigned step, unsigned nb)
{
    __syncthreads();
    if (threadIdx.x == 0) {
        __threadfence();
        unsigned old;
        asm volatile("atom.add.release.gpu.u32 %0, [%1], 1;"
                     : "=r"(old) : "l"(cnt) : "memory");
        if (old == step * nb - 1) {
            asm volatile("st.release.gpu.u32 [%0], %1;" :: "l"(gen), "r"(step) : "memory");
        } else {
            unsigned v;
            do {
                asm volatile("ld.acquire.gpu.u32 %0, [%1];" : "=r"(v) : "l"(gen) : "memory");
            } while (v < step);
        }
    }
    __syncthreads();
}

// ---------------- prep ----------------
__global__ void prep_k(const int* __restrict__ src, const int* __restrict__ trg,
                       float* __restrict__ out)
{
    if (blockIdx.x == 0 && threadIdx.x == 0) {
#if HAS_TC
        g_has_tc = 1;
#else
        g_has_tc = 0;
#endif
    }
    long idx = (long)blockIdx.x * blockDim.x + threadIdx.x;
    const long N0 = (long)B_ * V_;
    if (idx < N0) {
        long b = idx / V_, v = idx - b * V_;
        out[(size_t)b * T_ * V_ + v] = 0.f;
        return;
    }
    idx -= N0;
    if (idx < 2 * H_ * B_) { g_enc_hT[idx >> 14][0][idx & 16383] = 0.f; return; }
    idx -= 2 * H_ * B_;
    if (idx < S_ * B_) {
        int t = (int)(idx / B_), b = (int)(idx % B_);
        g_enc_rowidx[idx] = src[b * S_ + t];
        return;
    }
    idx -= S_ * B_;
    if (idx < TD * B_) {
        int t = (int)(idx / B_), b = (int)(idx % B_);
        g_dec_rowidx[idx] = trg[b * T_ + t];
        return;
    }
    idx -= TD * B_;
    if (idx < 192) { g_sync[idx] = 0; return; }
    idx -= 192;
    if (idx < (MPAD - MROWS) * 2048) {
        g_Abig[(size_t)(MROWS + (idx >> 11)) * 2048 + (idx & 2047)] = __float2bfloat16(0.f);
        return;
    }
}

// ---------------- W split conversion ----------------
__global__ void wconv_k(const float* __restrict__ fcW)
{
    size_t i = (size_t)blockIdx.x * 256 + threadIdx.x;
    if (i >= (size_t)V_ * 256) return;
    size_t n = i >> 8; int k4 = (int)(i & 255);
    float4 v = __ldcg((const float4*)fcW + i);
    __nv_bfloat16 h0 = __float2bfloat16(v.x), h1 = __float2bfloat16(v.y);
    __nv_bfloat16 h2 = __float2bfloat16(v.z), h3 = __float2bfloat16(v.w);
    __nv_bfloat16 l0 = __float2bfloat16(v.x - __bfloat162float(h0));
    __nv_bfloat16 l1 = __float2bfloat16(v.y - __bfloat162float(h1));
    __nv_bfloat16 l2 = __float2bfloat16(v.z - __bfloat162float(h2));
    __nv_bfloat16 l3 = __float2bfloat16(v.w - __bfloat162float(h3));
    __nv_bfloat162* dh = (__nv_bfloat162*)(g_Wbig + n * 2048 + k4 * 4);
    __nv_bfloat162* dl = (__nv_bfloat162*)(g_Wbig + n * 2048 + 1024 + k4 * 4);
    __nv_bfloat162 a; a.x = h0; a.y = h1; dh[0] = a;
    __nv_bfloat162 b; b.x = h2; b.y = h3; dh[1] = b;
    __nv_bfloat162 c; c.x = l0; c.y = l1; dl[0] = c;
    __nv_bfloat162 d; d.x = l2; d.y = l3; dl[1] = d;
}

// ---------------- pregate SGEMM (transposed output [t][gate][b]) ----------------
__global__ void sgemm_k(const float* __restrict__ A, const float* __restrict__ W,
                        const float* __restrict__ bias, const int* __restrict__ rowidx,
                        float* __restrict__ C, int M, int N, int K)
{
    __shared__ float As[16][128];
    __shared__ float Bs[16][128];
    const int tid = threadIdx.x;
    const int m0 = blockIdx.y * 128, n0 = blockIdx.x * 128;
    const int lm = tid & 127, lq = tid >> 7;
    int mm = m0 + lm; if (mm >= M) mm = M - 1;
    const float* aptr = A + (size_t)rowidx[mm] * K;
    const float* bptr = W + (size_t)(n0 + lm) * K;
    const int tx = tid & 15, ty = tid >> 4;
    float acc[8][8];
#pragma unroll
    for (int i = 0; i < 8; i++)
#pragma unroll
        for (int j = 0; j < 8; j++) acc[i][j] = 0.f;

    for (int k0 = 0; k0 < K; k0 += 16) {
        float4 a0 = *(const float4*)(aptr + k0 + 4 * lq);
        float4 a1 = *(const float4*)(aptr + k0 + 4 * lq + 8);
        float4 b0 = *(const float4*)(bptr + k0 + 4 * lq);
        float4 b1 = *(const float4*)(bptr + k0 + 4 * lq + 8);
        __syncthreads();
        As[4 * lq + 0][lm] = a0.x; As[4 * lq + 1][lm] = a0.y;
        As[4 * lq + 2][lm] = a0.z; As[4 * lq + 3][lm] = a0.w;
        As[4 * lq + 8][lm] = a1.x; As[4 * lq + 9][lm] = a1.y;
        As[4 * lq + 10][lm] = a1.z; As[4 * lq + 11][lm] = a1.w;
        Bs[4 * lq + 0][lm] = b0.x; Bs[4 * lq + 1][lm] = b0.y;
        Bs[4 * lq + 2][lm] = b0.z; Bs[4 * lq + 3][lm] = b0.w;
        Bs[4 * lq + 8][lm] = b1.x; Bs[4 * lq + 9][lm] = b1.y;
        Bs[4 * lq + 10][lm] = b1.z; Bs[4 * lq + 11][lm] = b1.w;
        __syncthreads();
#pragma unroll
        for (int k = 0; k < 16; k++) {
            float ar[8], br[8];
            *(float4*)&ar[0] = *(const float4*)&As[k][ty * 8];
            *(float4*)&ar[4] = *(const float4*)&As[k][ty * 8 + 4];
            *(float4*)&br[0] = *(const float4*)&Bs[k][tx * 8];
            *(float4*)&br[4] = *(const float4*)&Bs[k][tx * 8 + 4];
#pragma unroll
            for (int i = 0; i < 8; i++)
#pragma unroll
                for (int j = 0; j < 8; j++) acc[i][j] += ar[i] * br[j];
        }
    }
#pragma unroll
    for (int i = 0; i < 8; i++) {
        int m = m0 + ty * 8 + i;
        if (m >= M) break;
        int t = m >> 5, b = m & 31;
        const float* bp = bias + n0 + tx * 8;
#pragma unroll
        for (int j = 0; j < 8; j++)
            C[((size_t)t * N + (n0 + tx * 8 + j)) * B_ + b] = acc[i][j] + bp[j];
    }
}

// ---------------- persistent encoder (per-direction barriers, nb=64) ----------------
__global__ void enc_persist_k(const float* __restrict__ Whh_f,
                              const float* __restrict__ Whh_b)
{
    extern __shared__ float shT[];
    const int dir = blockIdx.x >> 6, cb = blockIdx.x & 63;
    const int w = threadIdx.x >> 5, lane = threadIdx.x & 31;
    const int j = cb * 8 + w;
    const float* Whh = dir ? Whh_b : Whh_f;
    const float* preBase = dir ? g_pre_bT : g_pre_fT;
    unsigned* cnt = &g_sync[dir * 64];
    unsigned* gen = &g_sync[dir * 64 + 32];
    const float4* wi = (const float4*)(Whh + (size_t)j * H_);
    const float4* wf = (const float4*)(Whh + (size_t)(H_ + j) * H_);
    const float4* wg = (const float4*)(Whh + (size_t)(2 * H_ + j) * H_);
    const float4* wo = (const float4*)(Whh + (size_t)(3 * H_ + j) * H_);
    float cst = 0.f;

    for (int s = 0; s < S_; s++) {
        const float4* s4 = (const float4*)g_enc_hT[dir][s & 1];
        float4* d4 = (float4*)shT;
        for (int i = threadIdx.x; i < H_ * B_ / 4; i += 256) d4[i] = __ldcg(s4 + i);
        __syncthreads();
        const int t = dir ? (S_ - 1 - s) : s;
        const float* preT = preBase + (size_t)t * GH * B_;
        float ai = __ldcg(preT + (size_t)(0 * H_ + j) * B_ + lane);
        float af = __ldcg(preT + (size_t)(1 * H_ + j) * B_ + lane);
        float ag = __ldcg(preT + (size_t)(2 * H_ + j) * B_ + lane);
        float ao = __ldcg(preT + (size_t)(3 * H_ + j) * B_ + lane);
#pragma unroll 4
        for (int k4 = 0; k4 < H_ / 4; k4++) {
            float4 a = wi[k4], f = wf[k4], g = wg[k4], o = wo[k4];
            float h0 = shT[(k4 * 4 + 0) * B_ + lane];
            float h1 = shT[(k4 * 4 + 1) * B_ + lane];
            float h2 = shT[(k4 * 4 + 2) * B_ + lane];
            float h3 = shT[(k4 * 4 + 3) * B_ + lane];
            ai += h0 * a.x + h1 * a.y + h2 * a.z + h3 * a.w;
            af += h0 * f.x + h1 * f.y + h2 * f.z + h3 * f.w;
            ag += h0 * g.x + h1 * g.y + h2 * g.z + h3 * g.w;
            ao += h0 * o.x + h1 * o.y + h2 * o.z + h3 * o.w;
        }
        float iv = 1.f / (1.f + expf(-ai));
        float fv = 1.f / (1.f + expf(-af));
        float gv = tanhf(ag);
        float ov = 1.f / (1.f + expf(-ao));
        cst = fv * cst + iv * gv;
        g_enc_hT[dir][(s + 1) & 1][(size_t)j * B_ + lane] = ov * tanhf(cst);
        if (s == S_ - 1) g_enc_cT[dir][(size_t)j * B_ + lane] = cst;
        grid_barrier2(cnt, gen, (unsigned)(s + 1), 64u);
    }
}

// ---------------- persistent decoder (nb=128) ----------------
__global__ void dec_persist_k(const float* __restrict__ Whh)
{
    extern __shared__ float shT[];
    const int w = threadIdx.x >> 5, lane = threadIdx.x & 31;
    const int j = blockIdx.x * 8 + w;
    unsigned* cnt = &g_sync[128];
    unsigned* gen = &g_sync[160];
    float cst, h0v;
    if (j < H_) { cst = g_enc_cT[0][j * B_ + lane]; h0v = g_enc_hT[0][0][j * B_ + lane]; }
    else { cst = g_enc_cT[1][(j - H_) * B_ + lane]; h0v = g_enc_hT[1][0][(j - H_) * B_ + lane]; }
    g_dec_hT[0][(size_t)j * B_ + lane] = h0v;
    grid_barrier2(cnt, gen, 1u, 128u);

    const float4* wi = (const float4*)(Whh + (size_t)j * DH);
    const float4* wf = (const float4*)(Whh + (size_t)(DH + j) * DH);
    const float4* wg = (const float4*)(Whh + (size_t)(2 * DH + j) * DH);
    const float4* wo = (const float4*)(Whh + (size_t)(3 * DH + j) * DH);

    for (int t = 0; t < TD; t++) {
        const float4* s4 = (const float4*)g_dec_hT[t & 1];
        float4* d4 = (float4*)shT;
        for (int i = threadIdx.x; i < DH * B_ / 4; i += 256) d4[i] = __ldcg(s4 + i);
        __syncthreads();
        const float* preT = g_dec_preT + (size_t)t * DG * B_;
        float ai = __ldcg(preT + (size_t)(0 * DH + j) * B_ + lane);
        float af = __ldcg(preT + (size_t)(1 * DH + j) * B_ + lane);
        float ag = __ldcg(preT + (size_t)(2 * DH + j) * B_ + lane);
        float ao = __ldcg(preT + (size_t)(3 * DH + j) * B_ + lane);
#pragma unroll 4
        for (int k4 = 0; k4 < DH / 4; k4++) {
            float4 a = wi[k4], f = wf[k4], g = wg[k4], o = wo[k4];
            float h0 = shT[(k4 * 4 + 0) * B_ + lane];
            float h1 = shT[(k4 * 4 + 1) * B_ + lane];
            float h2 = shT[(k4 * 4 + 2) * B_ + lane];
            float h3 = shT[(k4 * 4 + 3) * B_ + lane];
            ai += h0 * a.x + h1 * a.y + h2 * a.z + h3 * a.w;
            af += h0 * f.x + h1 * f.y + h2 * f.z + h3 * f.w;
            ag += h0 * g.x + h1 * g.y + h2 * g.z + h3 * g.w;
            ao += h0 * o.x + h1 * o.y + h2 * o.z + h3 * o.w;
        }
        float iv = 1.f / (1.f + expf(-ai));
        float fv = 1.f / (1.f + expf(-af));
        float gv = tanhf(ag);
        float ov = 1.f / (1.f + expf(-ao));
        cst = fv * cst + iv * gv;
        float hv = ov * tanhf(cst);
        g_dec_hT[(t + 1) & 1][(size_t)j * B_ + lane] = hv;
        size_t m = (size_t)t * B_ + lane;
        __nv_bfloat16 hi = __float2bfloat16(hv);
        g_Abig[m * 2048 + j] = hi;
        g_Abig[m * 2048 + 1024 + j] = __float2bfloat16(hv - __bfloat162float(hi));
        grid_barrier2(cnt, gen, (unsigned)(t + 2), 128u);
    }
}

// ================= tcgen05 final GEMM =================
#define KCH    16
#define STAGE  98304
#define OFF_AHI0 0
#define OFF_AHI1 16384
#define OFF_ALO0 32768
#define OFF_ALO1 49152
#define OFF_WHI  65536
#define OFF_WLO  81920
#define SMEM_HDR 1024
#define SMEM_TC  (SMEM_HDR + 2 * STAGE)
#define IDESC_F16 ((1u<<4)|(1u<<7)|(1u<<10)|((128u/8)<<17)|((128u/16)<<24))

static __device__ __forceinline__ uint32_t swz(uint32_t x) { return x ^ ((x >> 3) & 0x70); }

__device__ __forceinline__ uint32_t smem_u32(const void* p)
{
    uint32_t a;
    asm("{ .reg .u64 t; cvta.to.shared.u64 t, %1; cvt.u32.u64 %0, t; }" : "=r"(a) : "l"(p));
    return a;
}
__device__ __forceinline__ void cp16(uint32_t dst, const void* src)
{
    asm volatile("cp.async.cg.shared.global [%0], [%1], 16;" :: "r"(dst), "l"(src));
}

#if HAS_TC
__device__ __forceinline__ uint32_t elect1()
{
    uint32_t p;
    asm volatile("{ .reg .pred p; elect.sync _|p, 0xFFFFFFFF; selp.b32 %0, 1, 0, p; }" : "=r"(p));
    return p;
}
__device__ __forceinline__ void mma_f16_ss(uint32_t d, uint64_t ad, uint64_t bd,
                                           uint32_t idesc, uint32_t en)
{
    asm volatile(
        "{\n\t.reg .pred p;\n\tsetp.ne.u32 p, %5, 0;\n\t"
        "tcgen05.mma.cta_group::1.kind::f16 [%0], %1, %2, %3, {%4,%4,%4,%4}, p;\n\t}"
        :: "r"(d), "l"(ad), "l"(bd), "r"(idesc), "r"(0u), "r"(en) : "memory");
}
#endif

__device__ __forceinline__ void load_chunk(const __nv_bfloat16* Ag, const __nv_bfloat16* Wg,
                                           int kc, uint32_t sbase, int tid)
{
    {
        const __nv_bfloat16* sA = Ag + (size_t)tid * 2048 + kc;
        uint32_t abase = sbase + ((tid < 128) ? OFF_AHI0 : OFF_AHI1);
        uint32_t lbase = sbase + ((tid < 128) ? OFF_ALO0 : OFF_ALO1);
        uint32_t r = (tid & 127) * 128;
#pragma unroll
        for (int g = 0; g < 8; g++) cp16(abase + swz(r + g * 16), sA + g * 8);
#pragma unroll
        for (int g = 0; g < 8; g++) cp16(lbase + swz(r + g * 16), sA + 1024 + g * 8);
    }
    {
        int rw = tid >> 1, g0 = (tid & 1) * 4;
        const __nv_bfloat16* sW = Wg + (size_t)rw * 2048 + kc + g0 * 8;
        uint32_t r = rw * 128 + g0 * 16;
#pragma unroll
        for (int g = 0; g < 4; g++) cp16(sbase + OFF_WHI + swz(r + g * 16), sW + g * 8);
#pragma unroll
        for (int g = 0; g < 4; g++) cp16(sbase + OFF_WLO + swz(r + g * 16), sW + 1024 + g * 8);
    }
    asm volatile("cp.async.commit_group;" ::: "memory");
}

__global__ __launch_bounds__(256, 1)
void bgemm_tc(const float* __restrict__ bias, float* __restrict__ out)
{
#if HAS_TC
    extern __shared__ __align__(1024) unsigned char sm[];
    const uint32_t sbase = smem_u32(sm);
    const int tid = threadIdx.x, wid = tid >> 5, lane = tid & 31;
    const int n0 = blockIdx.x * 128;
    const int m0g = blockIdx.y * 256;
    const __nv_bfloat16* Ag = g_Abig + (size_t)m0g * 2048;
    const __nv_bfloat16* Wg = g_Wbig + (size_t)n0 * 2048;

    if (wid == 0)
        asm volatile("tcgen05.alloc.cta_group::1.sync.aligned.shared::cta.b32 [%0], 512;"
                     :: "r"(sbase) : "memory");
    if (tid == 0) {
        asm volatile("mbarrier.init.shared.b64 [%0], 1;" :: "r"(sbase + 16) : "memory");
        asm volatile("mbarrier.init.shared.b64 [%0], 1;" :: "r"(sbase + 24) : "memory");
    }
    __syncthreads();
    uint32_t tmem;
    asm volatile("ld.shared.b32 %0, [%1];" : "=r"(tmem) : "r"(sbase));

    load_chunk(Ag, Wg, 0, sbase + SMEM_HDR, tid);
    load_chunk(Ag, Wg, 64, sbase + SMEM_HDR + STAGE, tid);

    int phase0 = 0, phase1 = 0;
    for (int c = 0; c < KCH; c++) {
        const int p = c & 1;
        if (c + 1 < KCH) asm volatile("cp.async.wait_group 1;" ::: "memory");
        else             asm volatile("cp.async.wait_group 0;" ::: "memory");
        __syncthreads();
        asm volatile("fence.proxy.async.shared::cta;" ::: "memory");

        if (wid == 0 && elect1()) {
            const uint32_t st = sbase + SMEM_HDR + p * STAGE;
            const uint64_t BASE = (uint64_t(2) << 61) | (uint64_t(1) << 46) |
                                  (uint64_t(64) << 32) | (uint64_t(1) << 16);
            uint64_t dAhi0 = BASE | (((st + OFF_AHI0) >> 4) & 0x3FFF);
            uint64_t dAhi1 = BASE | (((st + OFF_AHI1) >> 4) & 0x3FFF);
            uint64_t dAlo0 = BASE | (((st + OFF_ALO0) >> 4) & 0x3FFF);
            uint64_t dAlo1 = BASE | (((st + OFF_ALO1) >> 4) & 0x3FFF);
            uint64_t dWhi  = BASE | (((st + OFF_WHI) >> 4) & 0x3FFF);
            uint64_t dWlo  = BASE | (((st + OFF_WLO) >> 4) & 0x3FFF);
#pragma unroll
            for (int ks = 0; ks < 4; ks++) {
                uint32_t en0 = (c == 0 && ks == 0) ? 0u : 1u;
                mma_f16_ss(tmem + 0,   dAhi0 + ks * 2, dWhi + ks * 2, IDESC_F16, en0);
                mma_f16_ss(tmem + 128, dAhi1 + ks * 2, dWhi + ks * 2, IDESC_F16, en0);
                mma_f16_ss(tmem + 0,   dAhi0 + ks * 2, dWlo + ks * 2, IDESC_F16, 1u);
                mma_f16_ss(tmem + 128, dAhi1 + ks * 2, dWlo + ks * 2, IDESC_F16, 1u);
                mma_f16_ss(tmem + 0,   dAlo0 + ks * 2, dWhi + ks * 2, IDESC_F16, 1u);
                mma_f16_ss(tmem + 128, dAlo1 + ks * 2, dWhi + ks * 2, IDESC_F16, 1u);
            }
            asm volatile(
                "tcgen05.commit.cta_group::1.mbarrier::arrive::one.shared::cluster.b64 [%0];"
                :: "r"(sbase + 16 + p * 8) : "memory");
        }
        {
            uint32_t mb = sbase + 16 + p * 8;
            uint32_t ph = p ? phase1 : phase0;
            uint32_t done;
            asm volatile(
                "{\n\t.reg .pred q;\n\t"
                "mbarrier.try_wait.parity.shared.b64 q, [%1], %2, 0x989680;\n\t"
                "selp.b32 %0, 1, 0, q;\n\t}"
                : "=r"(done) : "r"(mb), "r"(ph) : "memory");
            while (!done) {
                asm volatile(
                    "{\n\t.reg .pred q;\n\t"
                    "mbarrier.try_wait.parity.shared.b64 q, [%1], %2, 0x989680;\n\t"
                    "selp.b32 %0, 1, 0, q;\n\t}"
                    : "=r"(done) : "r"(mb), "r"(ph) : "memory");
            }
            if (p) phase1 ^= 1; else phase0 ^= 1;
        }
        if (c + 2 < KCH)
            load_chunk(Ag, Wg, (c + 2) * 64, sbase + SMEM_HDR + p * STAGE, tid);
    }

    asm volatile("tcgen05.fence::after_thread_sync;" ::: "memory");
    {
        const int sub = tid >> 7;
        const int wiw = (tid >> 5) & 3;
        const int mrow = m0g + sub * 128 + wiw * 32 + lane;
        const uint32_t warp_off = ((uint32_t)(tid & 127) >> 5) << 21;
        const uint32_t dbase = tmem + sub * 128 + warp_off;
        if (mrow < MROWS) {
            const int t = mrow >> 5, b = mrow & 31;
            float* orow = out + (size_t)(b * T_ + t + 1) * V_ + n0;
#pragma unroll
            for (int q = 0; q < 4; q++) {
                uint32_t r[32];
                asm volatile(
                    "tcgen05.ld.sync.aligned.32x32b.x32.b32 "
                    "{%0,%1,%2,%3,%4,%5,%6,%7,%8,%9,%10,%11,%12,%13,%14,%15,"
                    "%16,%17,%18,%19,%20,%21,%22,%23,%24,%25,%26,%27,%28,%29,%30,%31}, [%32];"
                    : "=r"(r[0]), "=r"(r[1]), "=r"(r[2]), "=r"(r[3]), "=r"(r[4]), "=r"(r[5]),
                      "=r"(r[6]), "=r"(r[7]), "=r"(r[8]), "=r"(r[9]), "=r"(r[10]), "=r"(r[11]),
                      "=r"(r[12]), "=r"(r[13]), "=r"(r[14]), "=r"(r[15]), "=r"(r[16]), "=r"(r[17]),
                      "=r"(r[18]), "=r"(r[19]), "=r"(r[20]), "=r"(r[21]), "=r"(r[22]), "=r"(r[23]),
                      "=r"(r[24]), "=r"(r[25]), "=r"(r[26]), "=r"(r[27]), "=r"(r[28]), "=r"(r[29]),
                      "=r"(r[30]), "=r"(r[31])
                    : "r"(dbase + q * 32));
                asm volatile("tcgen05.wait::ld.sync.aligned;" ::: "memory");
#pragma unroll
                for (int c4 = 0; c4 < 8; c4++) {
                    const int n = q * 32 + c4 * 4;
                    float4 bb = *(const float4*)(bias + n0 + n);
                    float4 v;
                    v.x = __uint_as_float(r[c4 * 4 + 0]) + bb.x;
                    v.y = __uint_as_float(r[c4 * 4 + 1]) + bb.y;
                    v.z = __uint_as_float(r[c4 * 4 + 2]) + bb.z;
                    v.w = __uint_as_float(r[c4 * 4 + 3]) + bb.w;
                    *(float4*)(orow + n) = v;
                }
            }
        } else {
#pragma unroll
            for (int q = 0; q < 4; q++) {
                uint32_t r0;
                asm volatile("tcgen05.ld.sync.aligned.32x32b.x1.b32 {%0}, [%1];"
                             : "=r"(r0) : "r"(dbase + q * 32));
                asm volatile("tcgen05.wait::ld.sync.aligned;" ::: "memory");
            }
        }
    }
    __syncthreads();
    if (wid == 0) {
        asm volatile("tcgen05.relinquish_alloc_permit.cta_group::1.sync.aligned;" ::: "memory");
        asm volatile("tcgen05.dealloc.cta_group::1.sync.aligned.b32 %0, 512;" :: "r"(tmem));
    }
#endif  // HAS_TC
}

// ---------------- mma.sync fallback GEMM (runs only if tcgen05 pass absent) ----------------
__device__ __forceinline__ void ldsm4(uint32_t* r, uint32_t addr)
{
    asm volatile("ldmatrix.sync.aligned.m8n8.x4.shared.b16 {%0,%1,%2,%3}, [%4];"
                 : "=r"(r[0]), "=r"(r[1]), "=r"(r[2]), "=r"(r[3]) : "r"(addr));
}
__device__ __forceinline__ void mma16816(float* d, const uint32_t* a, uint32_t b0, uint32_t b1)
{
    asm volatile("mma.sync.aligned.m16n8k16.row.col.f32.bf16.bf16.f32 "
                 "{%0,%1,%2,%3},{%4,%5,%6,%7},{%8,%9},{%0,%1,%2,%3};"
                 : "+f"(d[0]), "+f"(d[1]), "+f"(d[2]), "+f"(d[3])
                 : "r"(a[0]), "r"(a[1]), "r"(a[2]), "r"(a[3]), "r"(b0), "r"(b1));
}

__global__ __launch_bounds__(256, 2)
void bgemm_mma(const float* __restrict__ bias, float* __restrict__ out)
{
    if (g_has_tc) return;
    __shared__ __align__(16) unsigned char smem[40960];
    const int tid = threadIdx.x, lane = tid & 31, w = tid >> 5;
    const int wm = w >> 2, wn = w & 3;
    const int n0 = blockIdx.x * 128, m0 = blockIdx.y * 128;

    float acc[4][4][4];
#pragma unroll
    for (int a = 0; a < 4; a++)
#pragma unroll
        for (int b = 0; b < 4; b++)
#pragma unroll
            for (int c = 0; c < 4; c++) acc[a][b][c] = 0.f;

    const int rowL = tid >> 2, c16 = tid & 3;
    const __nv_bfloat16* Ag0 = g_Abig + (size_t)(m0 + rowL) * 2048 + c16 * 8;
    const __nv_bfloat16* Ag1 = Ag0 + (size_t)64 * 2048;
    const __nv_bfloat16* Wg0 = g_Wbig + (size_t)(n0 + rowL) * 2048 + c16 * 8;
    const __nv_bfloat16* Wg1 = Wg0 + (size_t)64 * 2048;
    unsigned char* SA = smem;
    unsigned char* SB = smem + 20480;
    unsigned char* sa0 = SA + rowL * 80 + c16 * 16;
    unsigned char* sb0 = SB + rowL * 80 + c16 * 16;
    const uint32_t smbase = (uint32_t)__cvta_generic_to_shared(smem);
    const uint32_t uaA = smbase + (wm * 64 + (lane & 15)) * 80 + (lane >> 4) * 16;
    const uint32_t uaB = smbase + 20480 +
        (wn * 32 + (lane & 7) + ((lane & 16) ? 8 : 0)) * 80 + ((lane & 8) ? 16 : 0);

    {
        *(uint4*)(sa0) = *(const uint4*)(Ag0);
        *(uint4*)(sa0 + 5120) = *(const uint4*)(Ag1);
        *(uint4*)(sb0) = *(const uint4*)(Wg0);
        *(uint4*)(sb0 + 5120) = *(const uint4*)(Wg1);
    }
    __syncthreads();

    for (int c = 0; c < 96; c++) {
        uint4 av0, av1, wv0, wv1;
        const int nc = c + 1;
        if (nc < 96) {
            int blk = nc >> 5, kin = (nc & 31) * 32;
            int aoff = kin + ((blk == 2) ? 1024 : 0);
            int woff = kin + ((blk == 1) ? 1024 : 0);
            av0 = *(const uint4*)(Ag0 + aoff);
            av1 = *(const uint4*)(Ag1 + aoff);
            wv0 = *(const uint4*)(Wg0 + woff);
            wv1 = *(const uint4*)(Wg1 + woff);
        }
        const uint32_t stg = (c & 1) * 10240;
#pragma unroll
        for (int ks = 0; ks < 2; ks++) {
            uint32_t af[4][4], bf[2][4];
#pragma unroll
            for (int mt = 0; mt < 4; mt++) ldsm4(af[mt], uaA + stg + mt * 1280 + ks * 32);
#pragma unroll
            for (int p = 0; p < 2; p++) ldsm4(bf[p], uaB + stg + p * 1280 + ks * 32);
#pragma unroll
            for (int mt = 0; mt < 4; mt++)
#pragma unroll
                for (int nt = 0; nt < 4; nt++)
                    mma16816(acc[mt][nt], af[mt], bf[nt >> 1][(nt & 1) * 2],
                             bf[nt >> 1][(nt & 1) * 2 + 1]);
        }
        if (nc < 96) {
            const int ns = (nc & 1) * 10240;
            *(uint4*)(sa0 + ns) = av0;
            *(uint4*)(sa0 + ns + 5120) = av1;
            *(uint4*)(sb0 + ns) = wv0;
            *(uint4*)(sb0 + ns + 5120) = wv1;
        }
        __syncthreads();
    }

#pragma unroll
    for (int nt = 0; nt < 4; nt++) {
        const int n = n0 + wn * 32 + nt * 8 + (lane & 3) * 2;
        const float2 bb = *(const float2*)(bias + n);
#pragma unroll
        for (int mt = 0; mt < 4; mt++) {
#pragma unroll
            for (int half = 0; half < 2; half++) {
                const int m = m0 + wm * 64 + mt * 16 + (lane >> 2) + half * 8;
                if (m < MROWS) {
                    const int t = m >> 5, b = m & 31;
                    float2 v;
                    v.x = acc[mt][nt][half * 2 + 0] + bb.x;
                    v.y = acc[mt][nt][half * 2 + 1] + bb.y;
                    *(float2*)(out + (size_t)(b * T_ + t + 1) * V_ + n) = v;
                }
            }
        }
    }
}

// ---------------- launch ----------------
extern "C" void kernel_launch(void* const* d_in, const int* in_sizes, int n_in,
                              void* d_out, int out_size)
{
    (void)in_sizes; (void)n_in; (void)out_size;
    const int*   src     = (const int*)d_in[0];
    const int*   trg     = (const int*)d_in[1];
    const float* enc_emb = (const float*)d_in[2];
    const float* dec_emb = (const float*)d_in[3];
    const float* eWih_f  = (const float*)d_in[4];
    const float* eWhh_f  = (const float*)d_in[5];
    const float* eb_f    = (const float*)d_in[6];
    const float* eWih_b  = (const float*)d_in[7];
    const float* eWhh_b  = (const float*)d_in[8];
    const float* eb_b    = (const float*)d_in[9];
    const float* dWih    = (const float*)d_in[10];
    const float* dWhh    = (const float*)d_in[11];
    const float* db      = (const float*)d_in[12];
    const float* fcW     = (const float*)d_in[13];
    const float* fcb     = (const float*)d_in[14];
    float* out = (float*)d_out;

    cudaFuncSetAttribute(enc_persist_k, cudaFuncAttributeMaxDynamicSharedMemorySize,
                         H_ * B_ * 4);
    cudaFuncSetAttribute(dec_persist_k, cudaFuncAttributeMaxDynamicSharedMemorySize,
                         DH * B_ * 4);
    cudaFuncSetAttribute(bgemm_tc, cudaFuncAttributeMaxDynamicSharedMemorySize, SMEM_TC);

    void *p_pre_fT, *p_pre_bT, *p_dec_preT, *p_enc_ri, *p_dec_ri;
    cudaGetSymbolAddress(&p_pre_fT, g_pre_fT);
    cudaGetSymbolAddress(&p_pre_bT, g_pre_bT);
    cudaGetSymbolAddress(&p_dec_preT, g_dec_preT);
    cudaGetSymbolAddress(&p_enc_ri, g_enc_rowidx);
    cudaGetSymbolAddress(&p_dec_ri, g_dec_rowidx);

    long total = (long)B_ * V_ + 2L * H_ * B_ + (long)S_ * B_ + (long)TD * B_
               + 192 + (long)(MPAD - MROWS) * 2048;
    prep_k<<<(unsigned)((total + 255) / 256), 256>>>(src, trg, out);
    wconv_k<<<V_, 256>>>(fcW);

    sgemm_k<<<dim3(GH / 128, (S_ * B_) / 128), 256>>>(
        enc_emb, eWih_f, eb_f, (const int*)p_enc_ri, (float*)p_pre_fT, S_ * B_, GH, E_);
    sgemm_k<<<dim3(GH / 128, (S_ * B_) / 128), 256>>>(
        enc_emb, eWih_b, eb_b, (const int*)p_enc_ri, (float*)p_pre_bT, S_ * B_, GH, E_);
    sgemm_k<<<dim3(DG / 128, (TD * B_ + 127) / 128), 256>>>(
        dec_emb, dWih, db, (const int*)p_dec_ri, (float*)p_dec_preT, TD * B_, DG, E_);

    enc_persist_k<<<128, 256, H_ * B_ * 4>>>(eWhh_f, eWhh_b);
    dec_persist_k<<<128, 256, DH * B_ * 4>>>(dWhh);

    bgemm_tc<<<dim3(V_ / 128, MPAD / 256), 256, SMEM_TC>>>(fcb, out);
    bgemm_mma<<<dim3(V_ / 128, MPAD / 128), 256>>>(fcb, out);
}

// round 9
// speedup vs baseline: 2.3989x; 1.9329x over previous
#include <cuda_runtime.h>
#include <cuda_bf16.h>
#include <math.h>
#include <stdint.h>

#define B_  32
#define S_  128
#define T_  64
#define E_  256
#define H_  512
#define V_  32000
#define GH  2048
#define DH  1024
#define DG  4096
#define TD  63
#define MROWS 2016
#define MPAD  2048

// tcgen05 only legal in the compute_103a feature pass.
#if defined(__CUDA_ARCH_FEAT_SM103_ALL) || defined(__CUDA_ARCH_FEAT_SM100_ALL) || !defined(__CUDA_ARCH__)
#define HAS_TC 1
#else
#define HAS_TC 0
#endif

// ---------------- scratch ----------------
__device__ float g_pre_fT[(size_t)S_ * GH * B_];
__device__ float g_pre_bT[(size_t)S_ * GH * B_];
__device__ float g_dec_preT[(size_t)TD * DG * B_];
__device__ float g_enc_hT[2][2][H_ * B_];
__device__ float g_enc_cT[2][H_ * B_];
__device__ float g_dec_hT[2][DH * B_];
__device__ int   g_enc_rowidx[S_ * B_];
__device__ int   g_dec_rowidx[TD * B_];
__device__ __nv_bfloat16 g_Abig[(size_t)MPAD * 2048];   // [hi(1024) | lo(1024)]
__device__ __nv_bfloat16 g_Wbig[(size_t)V_ * 2048];     // [hi | lo]
// sync cells 128B apart: [0]=cnt_e0 [32]=gen_e0 [64]=cnt_e1 [96]=gen_e1 [128]=cnt_d [160]=gen_d
__device__ unsigned g_sync[192];

// ---------------- grid barrier (R7-proven: fence + acquire) ----------------
// __threadfence's CCTL.IVALL wipes L1 each step — harmless now: weights live in
// SMEM, all cross-SM data (h, pregates) is read via .cg (L2).
__device__ __forceinline__ void grid_barrier2(unsigned* cnt, unsigned* gen,
                                              unsigned step, unsigned nb)
{
    __syncthreads();
    if (threadIdx.x == 0) {
        __threadfence();
        unsigned old;
        asm volatile("atom.add.release.gpu.u32 %0, [%1], 1;"
                     : "=r"(old) : "l"(cnt) : "memory");
        if (old == step * nb - 1) {
            asm volatile("st.release.gpu.u32 [%0], %1;" :: "l"(gen), "r"(step) : "memory");
        } else {
            unsigned v;
            do {
                asm volatile("ld.acquire.gpu.u32 %0, [%1];" : "=r"(v) : "l"(gen) : "memory");
            } while (v < step);
        }
    }
    __syncthreads();
}

// ---------------- prep ----------------
__global__ void prep_k(const int* __restrict__ src, const int* __restrict__ trg,
                       float* __restrict__ out)
{
    long idx = (long)blockIdx.x * blockDim.x + threadIdx.x;
    const long N0 = (long)B_ * V_;
    if (idx < N0) {
        long b = idx / V_, v = idx - b * V_;
        out[(size_t)b * T_ * V_ + v] = 0.f;
        return;
    }
    idx -= N0;
    if (idx < 2 * H_ * B_) { g_enc_hT[idx >> 14][0][idx & 16383] = 0.f; return; }
    idx -= 2 * H_ * B_;
    if (idx < S_ * B_) {
        int t = (int)(idx / B_), b = (int)(idx % B_);
        g_enc_rowidx[idx] = src[b * S_ + t];
        return;
    }
    idx -= S_ * B_;
    if (idx < TD * B_) {
        int t = (int)(idx / B_), b = (int)(idx % B_);
        g_dec_rowidx[idx] = trg[b * T_ + t];
        return;
    }
    idx -= TD * B_;
    if (idx < 192) { g_sync[idx] = 0; return; }
    idx -= 192;
    if (idx < (MPAD - MROWS) * 2048) {
        g_Abig[(size_t)(MROWS + (idx >> 11)) * 2048 + (idx & 2047)] = __float2bfloat16(0.f);
        return;
    }
}

// ---------------- W split conversion ----------------
__global__ void wconv_k(const float* __restrict__ fcW)
{
    size_t i = (size_t)blockIdx.x * 256 + threadIdx.x;
    if (i >= (size_t)V_ * 256) return;
    size_t n = i >> 8; int k4 = (int)(i & 255);
    float4 v = __ldcg((const float4*)fcW + i);
    __nv_bfloat16 h0 = __float2bfloat16(v.x), h1 = __float2bfloat16(v.y);
    __nv_bfloat16 h2 = __float2bfloat16(v.z), h3 = __float2bfloat16(v.w);
    __nv_bfloat16 l0 = __float2bfloat16(v.x - __bfloat162float(h0));
    __nv_bfloat16 l1 = __float2bfloat16(v.y - __bfloat162float(h1));
    __nv_bfloat16 l2 = __float2bfloat16(v.z - __bfloat162float(h2));
    __nv_bfloat16 l3 = __float2bfloat16(v.w - __bfloat162float(h3));
    __nv_bfloat162* dh = (__nv_bfloat162*)(g_Wbig + n * 2048 + k4 * 4);
    __nv_bfloat162* dl = (__nv_bfloat162*)(g_Wbig + n * 2048 + 1024 + k4 * 4);
    __nv_bfloat162 a; a.x = h0; a.y = h1; dh[0] = a;
    __nv_bfloat162 b; b.x = h2; b.y = h3; dh[1] = b;
    __nv_bfloat162 c; c.x = l0; c.y = l1; dl[0] = c;
    __nv_bfloat162 d; d.x = l2; d.y = l3; dl[1] = d;
}

// ---------------- fused pregate SGEMMs ----------------
__global__ void sgemm3_k(const float* __restrict__ enc_emb, const float* __restrict__ dec_emb,
                         const float* __restrict__ W0, const float* __restrict__ b0,
                         const float* __restrict__ W1, const float* __restrict__ b1,
                         const float* __restrict__ W2, const float* __restrict__ b2,
                         const int* __restrict__ ri_enc, const int* __restrict__ ri_dec,
                         float* __restrict__ C0, float* __restrict__ C1, float* __restrict__ C2)
{
    const int z = blockIdx.z;
    const float *A, *W, *bias; const int* rowidx; float* C;
    int M, N;
    if (z == 0)      { if (blockIdx.x >= 16) return; A = enc_emb; W = W0; bias = b0; rowidx = ri_enc; C = C0; M = S_ * B_;  N = GH; }
    else if (z == 1) { if (blockIdx.x >= 16) return; A = enc_emb; W = W1; bias = b1; rowidx = ri_enc; C = C1; M = S_ * B_;  N = GH; }
    else             { if (blockIdx.y >= 16) return; A = dec_emb; W = W2; bias = b2; rowidx = ri_dec; C = C2; M = TD * B_; N = DG; }
    const int K = E_;

    __shared__ float As[16][128];
    __shared__ float Bs[16][128];
    const int tid = threadIdx.x;
    const int m0 = blockIdx.y * 128, n0 = blockIdx.x * 128;
    const int lm = tid & 127, lq = tid >> 7;
    int mm = m0 + lm; if (mm >= M) mm = M - 1;
    const float* aptr = A + (size_t)rowidx[mm] * K;
    const float* bptr = W + (size_t)(n0 + lm) * K;
    const int tx = tid & 15, ty = tid >> 4;
    float acc[8][8];
#pragma unroll
    for (int i = 0; i < 8; i++)
#pragma unroll
        for (int j = 0; j < 8; j++) acc[i][j] = 0.f;

    for (int k0 = 0; k0 < K; k0 += 16) {
        float4 a0 = *(const float4*)(aptr + k0 + 4 * lq);
        float4 a1 = *(const float4*)(aptr + k0 + 4 * lq + 8);
        float4 b0v = *(const float4*)(bptr + k0 + 4 * lq);
        float4 b1v = *(const float4*)(bptr + k0 + 4 * lq + 8);
        __syncthreads();
        As[4 * lq + 0][lm] = a0.x; As[4 * lq + 1][lm] = a0.y;
        As[4 * lq + 2][lm] = a0.z; As[4 * lq + 3][lm] = a0.w;
        As[4 * lq + 8][lm] = a1.x; As[4 * lq + 9][lm] = a1.y;
        As[4 * lq + 10][lm] = a1.z; As[4 * lq + 11][lm] = a1.w;
        Bs[4 * lq + 0][lm] = b0v.x; Bs[4 * lq + 1][lm] = b0v.y;
        Bs[4 * lq + 2][lm] = b0v.z; Bs[4 * lq + 3][lm] = b0v.w;
        Bs[4 * lq + 8][lm] = b1v.x; Bs[4 * lq + 9][lm] = b1v.y;
        Bs[4 * lq + 10][lm] = b1v.z; Bs[4 * lq + 11][lm] = b1v.w;
        __syncthreads();
#pragma unroll
        for (int k = 0; k < 16; k++) {
            float ar[8], br[8];
            *(float4*)&ar[0] = *(const float4*)&As[k][ty * 8];
            *(float4*)&ar[4] = *(const float4*)&As[k][ty * 8 + 4];
            *(float4*)&br[0] = *(const float4*)&Bs[k][tx * 8];
            *(float4*)&br[4] = *(const float4*)&Bs[k][tx * 8 + 4];
#pragma unroll
            for (int i = 0; i < 8; i++)
#pragma unroll
                for (int j = 0; j < 8; j++) acc[i][j] += ar[i] * br[j];
        }
    }
#pragma unroll
    for (int i = 0; i < 8; i++) {
        int m = m0 + ty * 8 + i;
        if (m >= M) break;
        int t = m >> 5, b = m & 31;
        const float* bp = bias + n0 + tx * 8;
#pragma unroll
        for (int j = 0; j < 8; j++)
            C[((size_t)t * N + (n0 + tx * 8 + j)) * B_ + b] = acc[i][j] + bp[j];
    }
}

// ---------------- persistent encoder: Whh in SMEM (IVALL-immune) ----------------
// smem: sw = 32 rows x 512 floats (64KB), shT = H*B floats (64KB)
__global__ void enc_persist_k(const float* __restrict__ Whh_f,
                              const float* __restrict__ Whh_b)
{
    extern __shared__ float smemf[];
    float* sw = smemf;
    float* shT = smemf + 32 * H_;
    const int dir = blockIdx.x >> 6, cb = blockIdx.x & 63;
    const int w = threadIdx.x >> 5, lane = threadIdx.x & 31;
    const int j = cb * 8 + w;
    const float* Whh = dir ? Whh_b : Whh_f;
    const float* preBase = dir ? g_pre_bT : g_pre_fT;
    unsigned* cnt = &g_sync[dir * 64];
    unsigned* gen = &g_sync[dir * 64 + 32];

    // stage weights once: rows r = wc*4+g at sw4[r*128 + c4]
    {
        const int base_j = cb * 8;
        for (int idx = threadIdx.x; idx < 32 * 128; idx += 256) {
            int r = idx >> 7, c4 = idx & 127;
            int wc = r >> 2, g = r & 3;
            ((float4*)sw)[idx] =
                *((const float4*)(Whh + (size_t)(g * H_ + base_j + wc) * H_) + c4);
        }
    }
    __syncthreads();

    const float4* swi = (const float4*)sw + (w * 4 + 0) * 128;
    const float4* swf = (const float4*)sw + (w * 4 + 1) * 128;
    const float4* swg = (const float4*)sw + (w * 4 + 2) * 128;
    const float4* swo = (const float4*)sw + (w * 4 + 3) * 128;
    float cst = 0.f;

    for (int s = 0; s < S_; s++) {
        const float4* s4 = (const float4*)g_enc_hT[dir][s & 1];
        float4* d4 = (float4*)shT;
        for (int i = threadIdx.x; i < H_ * B_ / 4; i += 256) d4[i] = __ldcg(s4 + i);
        __syncthreads();
        const int t = dir ? (S_ - 1 - s) : s;
        const float* preT = preBase + (size_t)t * GH * B_;
        float ai = __ldcg(preT + (size_t)(0 * H_ + j) * B_ + lane);
        float af = __ldcg(preT + (size_t)(1 * H_ + j) * B_ + lane);
        float ag = __ldcg(preT + (size_t)(2 * H_ + j) * B_ + lane);
        float ao = __ldcg(preT + (size_t)(3 * H_ + j) * B_ + lane);
#pragma unroll 4
        for (int k4 = 0; k4 < H_ / 4; k4++) {
            float4 a = swi[k4], f = swf[k4], g = swg[k4], o = swo[k4];
            float h0 = shT[(k4 * 4 + 0) * B_ + lane];
            float h1 = shT[(k4 * 4 + 1) * B_ + lane];
            float h2 = shT[(k4 * 4 + 2) * B_ + lane];
            float h3 = shT[(k4 * 4 + 3) * B_ + lane];
            ai += h0 * a.x + h1 * a.y + h2 * a.z + h3 * a.w;
            af += h0 * f.x + h1 * f.y + h2 * f.z + h3 * f.w;
            ag += h0 * g.x + h1 * g.y + h2 * g.z + h3 * g.w;
            ao += h0 * o.x + h1 * o.y + h2 * o.z + h3 * o.w;
        }
        float iv = 1.f / (1.f + expf(-ai));
        float fv = 1.f / (1.f + expf(-af));
        float gv = tanhf(ag);
        float ov = 1.f / (1.f + expf(-ao));
        cst = fv * cst + iv * gv;
        __stcg(&g_enc_hT[dir][(s + 1) & 1][(size_t)j * B_ + lane], ov * tanhf(cst));
        if (s == S_ - 1) g_enc_cT[dir][(size_t)j * B_ + lane] = cst;
        grid_barrier2(cnt, gen, (unsigned)(s + 1), 64u);
    }
}

// ---------------- persistent decoder: Whh in SMEM, h staged in 2 halves ----------------
// smem: sw = 32 rows x 1024 floats (128KB), shH = 512*32 floats (64KB)
__global__ void dec_persist_k(const float* __restrict__ Whh)
{
    extern __shared__ float smemf[];
    float* sw = smemf;
    float* shH = smemf + 32 * DH;
    const int w = threadIdx.x >> 5, lane = threadIdx.x & 31;
    const int j = blockIdx.x * 8 + w;
    unsigned* cnt = &g_sync[128];
    unsigned* gen = &g_sync[160];

    // stage weights once: rows r = wc*4+g at sw4[r*256 + c4]
    {
        const int base_j = blockIdx.x * 8;
        for (int idx = threadIdx.x; idx < 32 * 256; idx += 256) {
            int r = idx >> 8, c4 = idx & 255;
            int wc = r >> 2, g = r & 3;
            ((float4*)sw)[idx] =
                *((const float4*)(Whh + (size_t)(g * DH + base_j + wc) * DH) + c4);
        }
    }

    float cst, h0v;
    if (j < H_) { cst = g_enc_cT[0][j * B_ + lane]; h0v = g_enc_hT[0][0][j * B_ + lane]; }
    else { cst = g_enc_cT[1][(j - H_) * B_ + lane]; h0v = g_enc_hT[1][0][(j - H_) * B_ + lane]; }
    __stcg(&g_dec_hT[0][(size_t)j * B_ + lane], h0v);
    grid_barrier2(cnt, gen, 1u, 128u);

    const float4* sw4 = (const float4*)sw;

    for (int t = 0; t < TD; t++) {
        const float* preT = g_dec_preT + (size_t)t * DG * B_;
        float ai = __ldcg(preT + (size_t)(0 * DH + j) * B_ + lane);
        float af = __ldcg(preT + (size_t)(1 * DH + j) * B_ + lane);
        float ag = __ldcg(preT + (size_t)(2 * DH + j) * B_ + lane);
        float ao = __ldcg(preT + (size_t)(3 * DH + j) * B_ + lane);

#pragma unroll
        for (int half = 0; half < 2; half++) {
            const float4* s4 = (const float4*)g_dec_hT[t & 1] + half * 4096;
            float4* d4 = (float4*)shH;
            for (int i = threadIdx.x; i < 4096; i += 256) d4[i] = __ldcg(s4 + i);
            __syncthreads();
            const float4* wi = sw4 + (w * 4 + 0) * 256 + half * 128;
            const float4* wf = sw4 + (w * 4 + 1) * 256 + half * 128;
            const float4* wg = sw4 + (w * 4 + 2) * 256 + half * 128;
            const float4* wo = sw4 + (w * 4 + 3) * 256 + half * 128;
#pragma unroll 4
            for (int k4 = 0; k4 < 128; k4++) {
                float4 a = wi[k4], f = wf[k4], g = wg[k4], o = wo[k4];
                float h0 = shH[(k4 * 4 + 0) * B_ + lane];
                float h1 = shH[(k4 * 4 + 1) * B_ + lane];
                float h2 = shH[(k4 * 4 + 2) * B_ + lane];
                float h3 = shH[(k4 * 4 + 3) * B_ + lane];
                ai += h0 * a.x + h1 * a.y + h2 * a.z + h3 * a.w;
                af += h0 * f.x + h1 * f.y + h2 * f.z + h3 * f.w;
                ag += h0 * g.x + h1 * g.y + h2 * g.z + h3 * g.w;
                ao += h0 * o.x + h1 * o.y + h2 * o.z + h3 * o.w;
            }
            if (half == 0) __syncthreads();   // shH reused; half=1 covered by barrier
        }

        float iv = 1.f / (1.f + expf(-ai));
        float fv = 1.f / (1.f + expf(-af));
        float gv = tanhf(ag);
        float ov = 1.f / (1.f + expf(-ao));
        cst = fv * cst + iv * gv;
        float hv = ov * tanhf(cst);
        __stcg(&g_dec_hT[(t + 1) & 1][(size_t)j * B_ + lane], hv);
        size_t m = (size_t)t * B_ + lane;
        __nv_bfloat16 hi = __float2bfloat16(hv);
        g_Abig[m * 2048 + j] = hi;
        g_Abig[m * 2048 + 1024 + j] = __float2bfloat16(hv - __bfloat162float(hi));
        grid_barrier2(cnt, gen, (unsigned)(t + 2), 128u);
    }
}

// ================= tcgen05 final GEMM =================
#define KCH    16
#define STAGE  98304
#define OFF_AHI0 0
#define OFF_AHI1 16384
#define OFF_ALO0 32768
#define OFF_ALO1 49152
#define OFF_WHI  65536
#define OFF_WLO  81920
#define SMEM_HDR 1024
#define SMEM_TC  (SMEM_HDR + 2 * STAGE)
#define IDESC_F16 ((1u<<4)|(1u<<7)|(1u<<10)|((128u/8)<<17)|((128u/16)<<24))

static __device__ __forceinline__ uint32_t swz(uint32_t x) { return x ^ ((x >> 3) & 0x70); }

__device__ __forceinline__ uint32_t smem_u32(const void* p)
{
    uint32_t a;
    asm("{ .reg .u64 t; cvta.to.shared.u64 t, %1; cvt.u32.u64 %0, t; }" : "=r"(a) : "l"(p));
    return a;
}
__device__ __forceinline__ void cp16(uint32_t dst, const void* src)
{
    asm volatile("cp.async.cg.shared.global [%0], [%1], 16;" :: "r"(dst), "l"(src));
}

#if HAS_TC
__device__ __forceinline__ uint32_t elect1()
{
    uint32_t p;
    asm volatile("{ .reg .pred p; elect.sync _|p, 0xFFFFFFFF; selp.b32 %0, 1, 0, p; }" : "=r"(p));
    return p;
}
__device__ __forceinline__ void mma_f16_ss(uint32_t d, uint64_t ad, uint64_t bd,
                                           uint32_t idesc, uint32_t en)
{
    asm volatile(
        "{\n\t.reg .pred p;\n\tsetp.ne.u32 p, %5, 0;\n\t"
        "tcgen05.mma.cta_group::1.kind::f16 [%0], %1, %2, %3, {%4,%4,%4,%4}, p;\n\t}"
        :: "r"(d), "l"(ad), "l"(bd), "r"(idesc), "r"(0u), "r"(en) : "memory");
}
#endif

__device__ __forceinline__ void load_chunk(const __nv_bfloat16* Ag, const __nv_bfloat16* Wg,
                                           int kc, uint32_t sbase, int tid)
{
    {
        const __nv_bfloat16* sA = Ag + (size_t)tid * 2048 + kc;
        uint32_t abase = sbase + ((tid < 128) ? OFF_AHI0 : OFF_AHI1);
        uint32_t lbase = sbase + ((tid < 128) ? OFF_ALO0 : OFF_ALO1);
        uint32_t r = (tid & 127) * 128;
#pragma unroll
        for (int g = 0; g < 8; g++) cp16(abase + swz(r + g * 16), sA + g * 8);
#pragma unroll
        for (int g = 0; g < 8; g++) cp16(lbase + swz(r + g * 16), sA + 1024 + g * 8);
    }
    {
        int rw = tid >> 1, g0 = (tid & 1) * 4;
        const __nv_bfloat16* sW = Wg + (size_t)rw * 2048 + kc + g0 * 8;
        uint32_t r = rw * 128 + g0 * 16;
#pragma unroll
        for (int g = 0; g < 4; g++) cp16(sbase + OFF_WHI + swz(r + g * 16), sW + g * 8);
#pragma unroll
        for (int g = 0; g < 4; g++) cp16(sbase + OFF_WLO + swz(r + g * 16), sW + 1024 + g * 8);
    }
    asm volatile("cp.async.commit_group;" ::: "memory");
}

__global__ __launch_bounds__(256, 1)
void bgemm_tc(const float* __restrict__ bias, float* __restrict__ out)
{
#if HAS_TC
    extern __shared__ __align__(1024) unsigned char sm[];
    const uint32_t sbase = smem_u32(sm);
    const int tid = threadIdx.x, wid = tid >> 5, lane = tid & 31;
    const int n0 = blockIdx.x * 128;
    const int m0g = blockIdx.y * 256;
    const __nv_bfloat16* Ag = g_Abig + (size_t)m0g * 2048;
    const __nv_bfloat16* Wg = g_Wbig + (size_t)n0 * 2048;

    if (wid == 0)
        asm volatile("tcgen05.alloc.cta_group::1.sync.aligned.shared::cta.b32 [%0], 512;"
                     :: "r"(sbase) : "memory");
    if (tid == 0) {
        asm volatile("mbarrier.init.shared.b64 [%0], 1;" :: "r"(sbase + 16) : "memory");
        asm volatile("mbarrier.init.shared.b64 [%0], 1;" :: "r"(sbase + 24) : "memory");
    }
    __syncthreads();
    uint32_t tmem;
    asm volatile("ld.shared.b32 %0, [%1];" : "=r"(tmem) : "r"(sbase));

    load_chunk(Ag, Wg, 0, sbase + SMEM_HDR, tid);
    load_chunk(Ag, Wg, 64, sbase + SMEM_HDR + STAGE, tid);

    int phase0 = 0, phase1 = 0;
    for (int c = 0; c < KCH; c++) {
        const int p = c & 1;
        if (c + 1 < KCH) asm volatile("cp.async.wait_group 1;" ::: "memory");
        else             asm volatile("cp.async.wait_group 0;" ::: "memory");
        __syncthreads();
        asm volatile("fence.proxy.async.shared::cta;" ::: "memory");

        if (wid == 0 && elect1()) {
            const uint32_t st = sbase + SMEM_HDR + p * STAGE;
            const uint64_t BASE = (uint64_t(2) << 61) | (uint64_t(1) << 46) |
                                  (uint64_t(64) << 32) | (uint64_t(1) << 16);
            uint64_t dAhi0 = BASE | (((st + OFF_AHI0) >> 4) & 0x3FFF);
            uint64_t dAhi1 = BASE | (((st + OFF_AHI1) >> 4) & 0x3FFF);
            uint64_t dAlo0 = BASE | (((st + OFF_ALO0) >> 4) & 0x3FFF);
            uint64_t dAlo1 = BASE | (((st + OFF_ALO1) >> 4) & 0x3FFF);
            uint64_t dWhi  = BASE | (((st + OFF_WHI) >> 4) & 0x3FFF);
            uint64_t dWlo  = BASE | (((st + OFF_WLO) >> 4) & 0x3FFF);
#pragma unroll
            for (int ks = 0; ks < 4; ks++) {
                uint32_t en0 = (c == 0 && ks == 0) ? 0u : 1u;
                mma_f16_ss(tmem + 0,   dAhi0 + ks * 2, dWhi + ks * 2, IDESC_F16, en0);
                mma_f16_ss(tmem + 128, dAhi1 + ks * 2, dWhi + ks * 2, IDESC_F16, en0);
                mma_f16_ss(tmem + 0,   dAhi0 + ks * 2, dWlo + ks * 2, IDESC_F16, 1u);
                mma_f16_ss(tmem + 128, dAhi1 + ks * 2, dWlo + ks * 2, IDESC_F16, 1u);
                mma_f16_ss(tmem + 0,   dAlo0 + ks * 2, dWhi + ks * 2, IDESC_F16, 1u);
                mma_f16_ss(tmem + 128, dAlo1 + ks * 2, dWhi + ks * 2, IDESC_F16, 1u);
            }
            asm volatile(
                "tcgen05.commit.cta_group::1.mbarrier::arrive::one.shared::cluster.b64 [%0];"
                :: "r"(sbase + 16 + p * 8) : "memory");
        }
        {
            uint32_t mb = sbase + 16 + p * 8;
            uint32_t ph = p ? phase1 : phase0;
            uint32_t done;
            asm volatile(
                "{\n\t.reg .pred q;\n\t"
                "mbarrier.try_wait.parity.shared.b64 q, [%1], %2, 0x989680;\n\t"
                "selp.b32 %0, 1, 0, q;\n\t}"
                : "=r"(done) : "r"(mb), "r"(ph) : "memory");
            while (!done) {
                asm volatile(
                    "{\n\t.reg .pred q;\n\t"
                    "mbarrier.try_wait.parity.shared.b64 q, [%1], %2, 0x989680;\n\t"
                    "selp.b32 %0, 1, 0, q;\n\t}"
                    : "=r"(done) : "r"(mb), "r"(ph) : "memory");
            }
            if (p) phase1 ^= 1; else phase0 ^= 1;
        }
        if (c + 2 < KCH)
            load_chunk(Ag, Wg, (c + 2) * 64, sbase + SMEM_HDR + p * STAGE, tid);
    }

    asm volatile("tcgen05.fence::after_thread_sync;" ::: "memory");
    {
        const int sub = tid >> 7;
        const int wiw = (tid >> 5) & 3;
        const int mrow = m0g + sub * 128 + wiw * 32 + lane;
        const uint32_t warp_off = ((uint32_t)(tid & 127) >> 5) << 21;
        const uint32_t dbase = tmem + sub * 128 + warp_off;
        if (mrow < MROWS) {
            const int t = mrow >> 5, b = mrow & 31;
            float* orow = out + (size_t)(b * T_ + t + 1) * V_ + n0;
#pragma unroll
            for (int q = 0; q < 4; q++) {
                uint32_t r[32];
                asm volatile(
                    "tcgen05.ld.sync.aligned.32x32b.x32.b32 "
                    "{%0,%1,%2,%3,%4,%5,%6,%7,%8,%9,%10,%11,%12,%13,%14,%15,"
                    "%16,%17,%18,%19,%20,%21,%22,%23,%24,%25,%26,%27,%28,%29,%30,%31}, [%32];"
                    : "=r"(r[0]), "=r"(r[1]), "=r"(r[2]), "=r"(r[3]), "=r"(r[4]), "=r"(r[5]),
                      "=r"(r[6]), "=r"(r[7]), "=r"(r[8]), "=r"(r[9]), "=r"(r[10]), "=r"(r[11]),
                      "=r"(r[12]), "=r"(r[13]), "=r"(r[14]), "=r"(r[15]), "=r"(r[16]), "=r"(r[17]),
                      "=r"(r[18]), "=r"(r[19]), "=r"(r[20]), "=r"(r[21]), "=r"(r[22]), "=r"(r[23]),
                      "=r"(r[24]), "=r"(r[25]), "=r"(r[26]), "=r"(r[27]), "=r"(r[28]), "=r"(r[29]),
                      "=r"(r[30]), "=r"(r[31])
                    : "r"(dbase + q * 32));
                asm volatile("tcgen05.wait::ld.sync.aligned;" ::: "memory");
#pragma unroll
                for (int c4 = 0; c4 < 8; c4++) {
                    const int n = q * 32 + c4 * 4;
                    float4 bb = *(const float4*)(bias + n0 + n);
                    float4 v;
                    v.x = __uint_as_float(r[c4 * 4 + 0]) + bb.x;
                    v.y = __uint_as_float(r[c4 * 4 + 1]) + bb.y;
                    v.z = __uint_as_float(r[c4 * 4 + 2]) + bb.z;
                    v.w = __uint_as_float(r[c4 * 4 + 3]) + bb.w;
                    *(float4*)(orow + n) = v;
                }
            }
        } else {
#pragma unroll
            for (int q = 0; q < 4; q++) {
                uint32_t r0;
                asm volatile("tcgen05.ld.sync.aligned.32x32b.x1.b32 {%0}, [%1];"
                             : "=r"(r0) : "r"(dbase + q * 32));
                asm volatile("tcgen05.wait::ld.sync.aligned;" ::: "memory");
            }
        }
    }
    __syncthreads();
    if (wid == 0) {
        asm volatile("tcgen05.relinquish_alloc_permit.cta_group::1.sync.aligned;" ::: "memory");
        asm volatile("tcgen05.dealloc.cta_group::1.sync.aligned.b32 %0, 512;" :: "r"(tmem));
    }
#endif  // HAS_TC
}

// ---------------- launch ----------------
extern "C" void kernel_launch(void* const* d_in, const int* in_sizes, int n_in,
                              void* d_out, int out_size)
{
    (void)in_sizes; (void)n_in; (void)out_size;
    const int*   src     = (const int*)d_in[0];
    const int*   trg     = (const int*)d_in[1];
    const float* enc_emb = (const float*)d_in[2];
    const float* dec_emb = (const float*)d_in[3];
    const float* eWih_f  = (const float*)d_in[4];
    const float* eWhh_f  = (const float*)d_in[5];
    const float* eb_f    = (const float*)d_in[6];
    const float* eWih_b  = (const float*)d_in[7];
    const float* eWhh_b  = (const float*)d_in[8];
    const float* eb_b    = (const float*)d_in[9];
    const float* dWih    = (const float*)d_in[10];
    const float* dWhh    = (const float*)d_in[11];
    const float* db      = (const float*)d_in[12];
    const float* fcW     = (const float*)d_in[13];
    const float* fcb     = (const float*)d_in[14];
    float* out = (float*)d_out;

    cudaFuncSetAttribute(enc_persist_k, cudaFuncAttributeMaxDynamicSharedMemorySize,
                         (32 * H_ + H_ * B_) * 4);          // 128 KB
    cudaFuncSetAttribute(dec_persist_k, cudaFuncAttributeMaxDynamicSharedMemorySize,
                         (32 * DH + 512 * B_) * 4);         // 192 KB
    cudaFuncSetAttribute(bgemm_tc, cudaFuncAttributeMaxDynamicSharedMemorySize, SMEM_TC);

    void *p_pre_fT, *p_pre_bT, *p_dec_preT, *p_enc_ri, *p_dec_ri;
    cudaGetSymbolAddress(&p_pre_fT, g_pre_fT);
    cudaGetSymbolAddress(&p_pre_bT, g_pre_bT);
    cudaGetSymbolAddress(&p_dec_preT, g_dec_preT);
    cudaGetSymbolAddress(&p_enc_ri, g_enc_rowidx);
    cudaGetSymbolAddress(&p_dec_ri, g_dec_rowidx);

    long total = (long)B_ * V_ + 2L * H_ * B_ + (long)S_ * B_ + (long)TD * B_
               + 192 + (long)(MPAD - MROWS) * 2048;
    prep_k<<<(unsigned)((total + 255) / 256), 256>>>(src, trg, out);
    wconv_k<<<V_, 256>>>(fcW);

    sgemm3_k<<<dim3(32, 32, 3), 256>>>(
        enc_emb, dec_emb, eWih_f, eb_f, eWih_b, eb_b, dWih, db,
        (const int*)p_enc_ri, (const int*)p_dec_ri,
        (float*)p_pre_fT, (float*)p_pre_bT, (float*)p_dec_preT);

    enc_persist_k<<<128, 256, (32 * H_ + H_ * B_) * 4>>>(eWhh_f, eWhh_b);
    dec_persist_k<<<128, 256, (32 * DH + 512 * B_) * 4>>>(dWhh);

    bgemm_tc<<<dim3(V_ / 128, MPAD / 256), 256, SMEM_TC>>>(fcb, out);
}

// round 10
// speedup vs baseline: 2.5596x; 1.0670x over previous
#include <cuda_runtime.h>
#include <cuda_bf16.h>
#include <math.h>
#include <stdint.h>

#define B_  32
#define S_  128
#define T_  64
#define E_  256
#define H_  512
#define V_  32000
#define GH  2048
#define DH  1024
#define DG  4096
#define TD  63
#define MROWS 2016
#define MPAD  2048

// tcgen05 only legal in the compute_103a feature pass.
#if defined(__CUDA_ARCH_FEAT_SM103_ALL) || defined(__CUDA_ARCH_FEAT_SM100_ALL) || !defined(__CUDA_ARCH__)
#define HAS_TC 1
#else
#define HAS_TC 0
#endif

// ---------------- scratch ----------------
__device__ float g_pre_fT[(size_t)S_ * GH * B_];
__device__ float g_pre_bT[(size_t)S_ * GH * B_];
__device__ float g_dec_preT[(size_t)TD * DG * B_];
__device__ float g_enc_hT[2][2][H_ * B_];
__device__ float g_enc_cT[2][H_ * B_];
__device__ float g_dec_hT[2][DH * B_];
__device__ int   g_enc_rowidx[S_ * B_];
__device__ int   g_dec_rowidx[TD * B_];
__device__ __nv_bfloat16 g_Abig[(size_t)MPAD * 2048];   // [hi(1024) | lo(1024)]
__device__ __nv_bfloat16 g_Wbig[(size_t)V_ * 2048];     // [hi | lo]
__device__ unsigned g_sync[192];

// ---------------- grid barrier (R7/R9-proven: fence + acquire) ----------------
__device__ __forceinline__ void grid_barrier2(unsigned* cnt, unsigned* gen,
                                              unsigned step, unsigned nb)
{
    __syncthreads();
    if (threadIdx.x == 0) {
        __threadfence();
        unsigned old;
        asm volatile("atom.add.release.gpu.u32 %0, [%1], 1;"
                     : "=r"(old) : "l"(cnt) : "memory");
        if (old == step * nb - 1) {
            asm volatile("st.release.gpu.u32 [%0], %1;" :: "l"(gen), "r"(step) : "memory");
        } else {
            unsigned v;
            do {
                asm volatile("ld.acquire.gpu.u32 %0, [%1];" : "=r"(v) : "l"(gen) : "memory");
            } while (v < step);
        }
    }
    __syncthreads();
}

// ---------------- f32x2 packed helpers ----------------
__device__ __forceinline__ unsigned long long pk2(float lo, float hi)
{
    unsigned long long p;
    asm("mov.b64 %0, {%1, %2};" : "=l"(p) : "f"(lo), "f"(hi));
    return p;
}
__device__ __forceinline__ unsigned long long ffma2(unsigned long long a,
                                                    unsigned long long b,
                                                    unsigned long long c)
{
    unsigned long long d;
    asm("fma.rn.f32x2 %0, %1, %2, %3;" : "=l"(d) : "l"(a), "l"(b), "l"(c));
    return d;
}
__device__ __forceinline__ void unpk2(unsigned long long p, float& lo, float& hi)
{
    asm("mov.b64 {%0, %1}, %2;" : "=f"(lo), "=f"(hi) : "l"(p));
}

// ---------------- fast activations (MUFU; err ~1e-6; f32x2 keeps dots exact) ----------
__device__ __forceinline__ float fsig(float x)
{
    float e; asm("ex2.approx.f32 %0, %1;" : "=f"(e) : "f"(-1.4426950408889634f * x));
    float r; asm("rcp.approx.f32 %0, %1;" : "=f"(r) : "f"(1.f + e));
    return r;
}
__device__ __forceinline__ float ftanh(float x)
{
    float e; asm("ex2.approx.f32 %0, %1;" : "=f"(e) : "f"(2.8853900817779268f * x));
    float r; asm("rcp.approx.f32 %0, %1;" : "=f"(r) : "f"(1.f + e));
    return 1.f - 2.f * r;
}

// ---------------- prep ----------------
__global__ void prep_k(const int* __restrict__ src, const int* __restrict__ trg,
                       float* __restrict__ out)
{
    long idx = (long)blockIdx.x * blockDim.x + threadIdx.x;
    const long N0 = (long)B_ * V_;
    if (idx < N0) {
        long b = idx / V_, v = idx - b * V_;
        out[(size_t)b * T_ * V_ + v] = 0.f;
        return;
    }
    idx -= N0;
    if (idx < 2 * H_ * B_) { g_enc_hT[idx >> 14][0][idx & 16383] = 0.f; return; }
    idx -= 2 * H_ * B_;
    if (idx < S_ * B_) {
        int t = (int)(idx / B_), b = (int)(idx % B_);
        g_enc_rowidx[idx] = src[b * S_ + t];
        return;
    }
    idx -= S_ * B_;
    if (idx < TD * B_) {
        int t = (int)(idx / B_), b = (int)(idx % B_);
        g_dec_rowidx[idx] = trg[b * T_ + t];
        return;
    }
    idx -= TD * B_;
    if (idx < 192) { g_sync[idx] = 0; return; }
    idx -= 192;
    if (idx < (MPAD - MROWS) * 2048) {
        g_Abig[(size_t)(MROWS + (idx >> 11)) * 2048 + (idx & 2047)] = __float2bfloat16(0.f);
        return;
    }
}

// ---------------- W split conversion ----------------
__global__ void wconv_k(const float* __restrict__ fcW)
{
    size_t i = (size_t)blockIdx.x * 256 + threadIdx.x;
    if (i >= (size_t)V_ * 256) return;
    size_t n = i >> 8; int k4 = (int)(i & 255);
    float4 v = __ldcg((const float4*)fcW + i);
    __nv_bfloat16 h0 = __float2bfloat16(v.x), h1 = __float2bfloat16(v.y);
    __nv_bfloat16 h2 = __float2bfloat16(v.z), h3 = __float2bfloat16(v.w);
    __nv_bfloat16 l0 = __float2bfloat16(v.x - __bfloat162float(h0));
    __nv_bfloat16 l1 = __float2bfloat16(v.y - __bfloat162float(h1));
    __nv_bfloat16 l2 = __float2bfloat16(v.z - __bfloat162float(h2));
    __nv_bfloat16 l3 = __float2bfloat16(v.w - __bfloat162float(h3));
    __nv_bfloat162* dh = (__nv_bfloat162*)(g_Wbig + n * 2048 + k4 * 4);
    __nv_bfloat162* dl = (__nv_bfloat162*)(g_Wbig + n * 2048 + 1024 + k4 * 4);
    __nv_bfloat162 a; a.x = h0; a.y = h1; dh[0] = a;
    __nv_bfloat162 b; b.x = h2; b.y = h3; dh[1] = b;
    __nv_bfloat162 c; c.x = l0; c.y = l1; dl[0] = c;
    __nv_bfloat162 d; d.x = l2; d.y = l3; dl[1] = d;
}

// ---------------- fused pregate SGEMMs ----------------
__global__ void sgemm3_k(const float* __restrict__ enc_emb, const float* __restrict__ dec_emb,
                         const float* __restrict__ W0, const float* __restrict__ b0,
                         const float* __restrict__ W1, const float* __restrict__ b1,
                         const float* __restrict__ W2, const float* __restrict__ b2,
                         const int* __restrict__ ri_enc, const int* __restrict__ ri_dec,
                         float* __restrict__ C0, float* __restrict__ C1, float* __restrict__ C2)
{
    const int z = blockIdx.z;
    const float *A, *W, *bias; const int* rowidx; float* C;
    int M, N;
    if (z == 0)      { if (blockIdx.x >= 16) return; A = enc_emb; W = W0; bias = b0; rowidx = ri_enc; C = C0; M = S_ * B_;  N = GH; }
    else if (z == 1) { if (blockIdx.x >= 16) return; A = enc_emb; W = W1; bias = b1; rowidx = ri_enc; C = C1; M = S_ * B_;  N = GH; }
    else             { if (blockIdx.y >= 16) return; A = dec_emb; W = W2; bias = b2; rowidx = ri_dec; C = C2; M = TD * B_; N = DG; }
    const int K = E_;

    __shared__ float As[16][128];
    __shared__ float Bs[16][128];
    const int tid = threadIdx.x;
    const int m0 = blockIdx.y * 128, n0 = blockIdx.x * 128;
    const int lm = tid & 127, lq = tid >> 7;
    int mm = m0 + lm; if (mm >= M) mm = M - 1;
    const float* aptr = A + (size_t)rowidx[mm] * K;
    const float* bptr = W + (size_t)(n0 + lm) * K;
    const int tx = tid & 15, ty = tid >> 4;
    float acc[8][8];
#pragma unroll
    for (int i = 0; i < 8; i++)
#pragma unroll
        for (int j = 0; j < 8; j++) acc[i][j] = 0.f;

    for (int k0 = 0; k0 < K; k0 += 16) {
        float4 a0 = *(const float4*)(aptr + k0 + 4 * lq);
        float4 a1 = *(const float4*)(aptr + k0 + 4 * lq + 8);
        float4 b0v = *(const float4*)(bptr + k0 + 4 * lq);
        float4 b1v = *(const float4*)(bptr + k0 + 4 * lq + 8);
        __syncthreads();
        As[4 * lq + 0][lm] = a0.x; As[4 * lq + 1][lm] = a0.y;
        As[4 * lq + 2][lm] = a0.z; As[4 * lq + 3][lm] = a0.w;
        As[4 * lq + 8][lm] = a1.x; As[4 * lq + 9][lm] = a1.y;
        As[4 * lq + 10][lm] = a1.z; As[4 * lq + 11][lm] = a1.w;
        Bs[4 * lq + 0][lm] = b0v.x; Bs[4 * lq + 1][lm] = b0v.y;
        Bs[4 * lq + 2][lm] = b0v.z; Bs[4 * lq + 3][lm] = b0v.w;
        Bs[4 * lq + 8][lm] = b1v.x; Bs[4 * lq + 9][lm] = b1v.y;
        Bs[4 * lq + 10][lm] = b1v.z; Bs[4 * lq + 11][lm] = b1v.w;
        __syncthreads();
#pragma unroll
        for (int k = 0; k < 16; k++) {
            float ar[8], br[8];
            *(float4*)&ar[0] = *(const float4*)&As[k][ty * 8];
            *(float4*)&ar[4] = *(const float4*)&As[k][ty * 8 + 4];
            *(float4*)&br[0] = *(const float4*)&Bs[k][tx * 8];
            *(float4*)&br[4] = *(const float4*)&Bs[k][tx * 8 + 4];
#pragma unroll
            for (int i = 0; i < 8; i++)
#pragma unroll
                for (int j = 0; j < 8; j++) acc[i][j] += ar[i] * br[j];
        }
    }
#pragma unroll
    for (int i = 0; i < 8; i++) {
        int m = m0 + ty * 8 + i;
        if (m >= M) break;
        int t = m >> 5, b = m & 31;
        const float* bp = bias + n0 + tx * 8;
#pragma unroll
        for (int j = 0; j < 8; j++)
            C[((size_t)t * N + (n0 + tx * 8 + j)) * B_ + b] = acc[i][j] + bp[j];
    }
}

// ---------------- persistent encoder: packed-f32x2 gate dots ----------------
// smem: sw_if 8x512 float2 (32KB) | sw_go (32KB) | shT H*B floats (64KB) = 128KB
__global__ void enc_persist_k(const float* __restrict__ Whh_f,
                              const float* __restrict__ Whh_b)
{
    extern __shared__ float smemf[];
    float2* sw_if = (float2*)smemf;
    float2* sw_go = (float2*)(smemf + 8192);
    float*  shT   = smemf + 16384;
    const int dir = blockIdx.x >> 6, cb = blockIdx.x & 63;
    const int w = threadIdx.x >> 5, lane = threadIdx.x & 31;
    const int j = cb * 8 + w;
    const float* Whh = dir ? Whh_b : Whh_f;
    const float* preBase = dir ? g_pre_bT : g_pre_fT;
    unsigned* cnt = &g_sync[dir * 64];
    unsigned* gen = &g_sync[dir * 64 + 32];

    // stage interleaved weight pairs once
    {
        const int base_j = cb * 8;
        for (int idx = threadIdx.x; idx < 8 * H_; idx += 256) {
            int c = idx >> 9, k = idx & 511;
            float wi = Whh[(size_t)(0 * H_ + base_j + c) * H_ + k];
            float wf = Whh[(size_t)(1 * H_ + base_j + c) * H_ + k];
            float wg = Whh[(size_t)(2 * H_ + base_j + c) * H_ + k];
            float wo = Whh[(size_t)(3 * H_ + base_j + c) * H_ + k];
            sw_if[idx] = make_float2(wi, wf);
            sw_go[idx] = make_float2(wg, wo);
        }
    }
    __syncthreads();

    const ulonglong2* pif = (const ulonglong2*)(sw_if + (size_t)w * H_);
    const ulonglong2* pgo = (const ulonglong2*)(sw_go + (size_t)w * H_);
    float cst = 0.f;

    for (int s = 0; s < S_; s++) {
        const float4* s4 = (const float4*)g_enc_hT[dir][s & 1];
        float4* d4 = (float4*)shT;
        for (int i = threadIdx.x; i < H_ * B_ / 4; i += 256) d4[i] = __ldcg(s4 + i);
        __syncthreads();
        const int t = dir ? (S_ - 1 - s) : s;
        const float* preT = preBase + (size_t)t * GH * B_;
        unsigned long long acc_if = pk2(__ldcg(preT + (size_t)(0 * H_ + j) * B_ + lane),
                                        __ldcg(preT + (size_t)(1 * H_ + j) * B_ + lane));
        unsigned long long acc_go = pk2(__ldcg(preT + (size_t)(2 * H_ + j) * B_ + lane),
                                        __ldcg(preT + (size_t)(3 * H_ + j) * B_ + lane));
#pragma unroll 4
        for (int k4 = 0; k4 < H_ / 4; k4++) {
            ulonglong2 a01 = pif[k4 * 2], a23 = pif[k4 * 2 + 1];
            ulonglong2 g01 = pgo[k4 * 2], g23 = pgo[k4 * 2 + 1];
            float h0 = shT[(k4 * 4 + 0) * B_ + lane];
            float h1 = shT[(k4 * 4 + 1) * B_ + lane];
            float h2 = shT[(k4 * 4 + 2) * B_ + lane];
            float h3 = shT[(k4 * 4 + 3) * B_ + lane];
            unsigned long long H0 = pk2(h0, h0), H1 = pk2(h1, h1);
            unsigned long long H2 = pk2(h2, h2), H3 = pk2(h3, h3);
            acc_if = ffma2(a01.x, H0, acc_if);
            acc_if = ffma2(a01.y, H1, acc_if);
            acc_if = ffma2(a23.x, H2, acc_if);
            acc_if = ffma2(a23.y, H3, acc_if);
            acc_go = ffma2(g01.x, H0, acc_go);
            acc_go = ffma2(g01.y, H1, acc_go);
            acc_go = ffma2(g23.x, H2, acc_go);
            acc_go = ffma2(g23.y, H3, acc_go);
        }
        float ai, af, ag, ao;
        unpk2(acc_if, ai, af);
        unpk2(acc_go, ag, ao);
        float iv = fsig(ai), fv = fsig(af), gv = ftanh(ag), ov = fsig(ao);
        cst = fv * cst + iv * gv;
        __stcg(&g_enc_hT[dir][(s + 1) & 1][(size_t)j * B_ + lane], ov * ftanh(cst));
        if (s == S_ - 1) g_enc_cT[dir][(size_t)j * B_ + lane] = cst;
        grid_barrier2(cnt, gen, (unsigned)(s + 1), 64u);
    }
}

// ---------------- persistent decoder: packed-f32x2, h in 2 halves ----------------
// smem: sw_if 8x1024 float2 (64KB) | sw_go (64KB) | shH 512*32 floats (64KB) = 192KB
__global__ void dec_persist_k(const float* __restrict__ Whh)
{
    extern __shared__ float smemf[];
    float2* sw_if = (float2*)smemf;
    float2* sw_go = (float2*)(smemf + 16384);
    float*  shH   = smemf + 32768;
    const int w = threadIdx.x >> 5, lane = threadIdx.x & 31;
    const int j = blockIdx.x * 8 + w;
    unsigned* cnt = &g_sync[128];
    unsigned* gen = &g_sync[160];

    // stage interleaved weight pairs once
    {
        const int base_j = blockIdx.x * 8;
        for (int idx = threadIdx.x; idx < 8 * DH; idx += 256) {
            int c = idx >> 10, k = idx & 1023;
            float wi = Whh[(size_t)(0 * DH + base_j + c) * DH + k];
            float wf = Whh[(size_t)(1 * DH + base_j + c) * DH + k];
            float wg = Whh[(size_t)(2 * DH + base_j + c) * DH + k];
            float wo = Whh[(size_t)(3 * DH + base_j + c) * DH + k];
            sw_if[idx] = make_float2(wi, wf);
            sw_go[idx] = make_float2(wg, wo);
        }
    }

    float cst, h0v;
    if (j < H_) { cst = g_enc_cT[0][j * B_ + lane]; h0v = g_enc_hT[0][0][j * B_ + lane]; }
    else { cst = g_enc_cT[1][(j - H_) * B_ + lane]; h0v = g_enc_hT[1][0][(j - H_) * B_ + lane]; }
    __stcg(&g_dec_hT[0][(size_t)j * B_ + lane], h0v);
    grid_barrier2(cnt, gen, 1u, 128u);

    for (int t = 0; t < TD; t++) {
        const float* preT = g_dec_preT + (size_t)t * DG * B_;
        unsigned long long acc_if = pk2(__ldcg(preT + (size_t)(0 * DH + j) * B_ + lane),
                                        __ldcg(preT + (size_t)(1 * DH + j) * B_ + lane));
        unsigned long long acc_go = pk2(__ldcg(preT + (size_t)(2 * DH + j) * B_ + lane),
                                        __ldcg(preT + (size_t)(3 * DH + j) * B_ + lane));

#pragma unroll
        for (int half = 0; half < 2; half++) {
            const float4* s4 = (const float4*)g_dec_hT[t & 1] + half * 4096;
            float4* d4 = (float4*)shH;
            for (int i = threadIdx.x; i < 4096; i += 256) d4[i] = __ldcg(s4 + i);
            __syncthreads();
            const ulonglong2* pif =
                (const ulonglong2*)(sw_if + (size_t)w * DH) + half * 256;
            const ulonglong2* pgo =
                (const ulonglong2*)(sw_go + (size_t)w * DH) + half * 256;
#pragma unroll 4
            for (int k4 = 0; k4 < 128; k4++) {
                ulonglong2 a01 = pif[k4 * 2], a23 = pif[k4 * 2 + 1];
                ulonglong2 g01 = pgo[k4 * 2], g23 = pgo[k4 * 2 + 1];
                float h0 = shH[(k4 * 4 + 0) * B_ + lane];
                float h1 = shH[(k4 * 4 + 1) * B_ + lane];
                float h2 = shH[(k4 * 4 + 2) * B_ + lane];
                float h3 = shH[(k4 * 4 + 3) * B_ + lane];
                unsigned long long H0 = pk2(h0, h0), H1 = pk2(h1, h1);
                unsigned long long H2 = pk2(h2, h2), H3 = pk2(h3, h3);
                acc_if = ffma2(a01.x, H0, acc_if);
                acc_if = ffma2(a01.y, H1, acc_if);
                acc_if = ffma2(a23.x, H2, acc_if);
                acc_if = ffma2(a23.y, H3, acc_if);
                acc_go = ffma2(g01.x, H0, acc_go);
                acc_go = ffma2(g01.y, H1, acc_go);
                acc_go = ffma2(g23.x, H2, acc_go);
                acc_go = ffma2(g23.y, H3, acc_go);
            }
            if (half == 0) __syncthreads();   // shH reused; half=1 covered by barrier
        }

        float ai, af, ag, ao;
        unpk2(acc_if, ai, af);
        unpk2(acc_go, ag, ao);
        float iv = fsig(ai), fv = fsig(af), gv = ftanh(ag), ov = fsig(ao);
        cst = fv * cst + iv * gv;
        float hv = ov * ftanh(cst);
        __stcg(&g_dec_hT[(t + 1) & 1][(size_t)j * B_ + lane], hv);
        size_t m = (size_t)t * B_ + lane;
        __nv_bfloat16 hi = __float2bfloat16(hv);
        g_Abig[m * 2048 + j] = hi;
        g_Abig[m * 2048 + 1024 + j] = __float2bfloat16(hv - __bfloat162float(hi));
        grid_barrier2(cnt, gen, (unsigned)(t + 2), 128u);
    }
}

// ================= tcgen05 final GEMM (unchanged from R9) =================
#define KCH    16
#define STAGE  98304
#define OFF_AHI0 0
#define OFF_AHI1 16384
#define OFF_ALO0 32768
#define OFF_ALO1 49152
#define OFF_WHI  65536
#define OFF_WLO  81920
#define SMEM_HDR 1024
#define SMEM_TC  (SMEM_HDR + 2 * STAGE)
#define IDESC_F16 ((1u<<4)|(1u<<7)|(1u<<10)|((128u/8)<<17)|((128u/16)<<24))

static __device__ __forceinline__ uint32_t swz(uint32_t x) { return x ^ ((x >> 3) & 0x70); }

__device__ __forceinline__ uint32_t smem_u32(const void* p)
{
    uint32_t a;
    asm("{ .reg .u64 t; cvta.to.shared.u64 t, %1; cvt.u32.u64 %0, t; }" : "=r"(a) : "l"(p));
    return a;
}
__device__ __forceinline__ void cp16(uint32_t dst, const void* src)
{
    asm volatile("cp.async.cg.shared.global [%0], [%1], 16;" :: "r"(dst), "l"(src));
}

#if HAS_TC
__device__ __forceinline__ uint32_t elect1()
{
    uint32_t p;
    asm volatile("{ .reg .pred p; elect.sync _|p, 0xFFFFFFFF; selp.b32 %0, 1, 0, p; }" : "=r"(p));
    return p;
}
__device__ __forceinline__ void mma_f16_ss(uint32_t d, uint64_t ad, uint64_t bd,
                                           uint32_t idesc, uint32_t en)
{
    asm volatile(
        "{\n\t.reg .pred p;\n\tsetp.ne.u32 p, %5, 0;\n\t"
        "tcgen05.mma.cta_group::1.kind::f16 [%0], %1, %2, %3, {%4,%4,%4,%4}, p;\n\t}"
        :: "r"(d), "l"(ad), "l"(bd), "r"(idesc), "r"(0u), "r"(en) : "memory");
}
#endif

__device__ __forceinline__ void load_chunk(const __nv_bfloat16* Ag, const __nv_bfloat16* Wg,
                                           int kc, uint32_t sbase, int tid)
{
    {
        const __nv_bfloat16* sA = Ag + (size_t)tid * 2048 + kc;
        uint32_t abase = sbase + ((tid < 128) ? OFF_AHI0 : OFF_AHI1);
        uint32_t lbase = sbase + ((tid < 128) ? OFF_ALO0 : OFF_ALO1);
        uint32_t r = (tid & 127) * 128;
#pragma unroll
        for (int g = 0; g < 8; g++) cp16(abase + swz(r + g * 16), sA + g * 8);
#pragma unroll
        for (int g = 0; g < 8; g++) cp16(lbase + swz(r + g * 16), sA + 1024 + g * 8);
    }
    {
        int rw = tid >> 1, g0 = (tid & 1) * 4;
        const __nv_bfloat16* sW = Wg + (size_t)rw * 2048 + kc + g0 * 8;
        uint32_t r = rw * 128 + g0 * 16;
#pragma unroll
        for (int g = 0; g < 4; g++) cp16(sbase + OFF_WHI + swz(r + g * 16), sW + g * 8);
#pragma unroll
        for (int g = 0; g < 4; g++) cp16(sbase + OFF_WLO + swz(r + g * 16), sW + 1024 + g * 8);
    }
    asm volatile("cp.async.commit_group;" ::: "memory");
}

__global__ __launch_bounds__(256, 1)
void bgemm_tc(const float* __restrict__ bias, float* __restrict__ out)
{
#if HAS_TC
    extern __shared__ __align__(1024) unsigned char sm[];
    const uint32_t sbase = smem_u32(sm);
    const int tid = threadIdx.x, wid = tid >> 5, lane = tid & 31;
    const int n0 = blockIdx.x * 128;
    const int m0g = blockIdx.y * 256;
    const __nv_bfloat16* Ag = g_Abig + (size_t)m0g * 2048;
    const __nv_bfloat16* Wg = g_Wbig + (size_t)n0 * 2048;

    if (wid == 0)
        asm volatile("tcgen05.alloc.cta_group::1.sync.aligned.shared::cta.b32 [%0], 512;"
                     :: "r"(sbase) : "memory");
    if (tid == 0) {
        asm volatile("mbarrier.init.shared.b64 [%0], 1;" :: "r"(sbase + 16) : "memory");
        asm volatile("mbarrier.init.shared.b64 [%0], 1;" :: "r"(sbase + 24) : "memory");
    }
    __syncthreads();
    uint32_t tmem;
    asm volatile("ld.shared.b32 %0, [%1];" : "=r"(tmem) : "r"(sbase));

    load_chunk(Ag, Wg, 0, sbase + SMEM_HDR, tid);
    load_chunk(Ag, Wg, 64, sbase + SMEM_HDR + STAGE, tid);

    int phase0 = 0, phase1 = 0;
    for (int c = 0; c < KCH; c++) {
        const int p = c & 1;
        if (c + 1 < KCH) asm volatile("cp.async.wait_group 1;" ::: "memory");
        else             asm volatile("cp.async.wait_group 0;" ::: "memory");
        __syncthreads();
        asm volatile("fence.proxy.async.shared::cta;" ::: "memory");

        if (wid == 0 && elect1()) {
            const uint32_t st = sbase + SMEM_HDR + p * STAGE;
            const uint64_t BASE = (uint64_t(2) << 61) | (uint64_t(1) << 46) |
                                  (uint64_t(64) << 32) | (uint64_t(1) << 16);
            uint64_t dAhi0 = BASE | (((st + OFF_AHI0) >> 4) & 0x3FFF);
            uint64_t dAhi1 = BASE | (((st + OFF_AHI1) >> 4) & 0x3FFF);
            uint64_t dAlo0 = BASE | (((st + OFF_ALO0) >> 4) & 0x3FFF);
            uint64_t dAlo1 = BASE | (((st + OFF_ALO1) >> 4) & 0x3FFF);
            uint64_t dWhi  = BASE | (((st + OFF_WHI) >> 4) & 0x3FFF);
            uint64_t dWlo  = BASE | (((st + OFF_WLO) >> 4) & 0x3FFF);
#pragma unroll
            for (int ks = 0; ks < 4; ks++) {
                uint32_t en0 = (c == 0 && ks == 0) ? 0u : 1u;
                mma_f16_ss(tmem + 0,   dAhi0 + ks * 2, dWhi + ks * 2, IDESC_F16, en0);
                mma_f16_ss(tmem + 128, dAhi1 + ks * 2, dWhi + ks * 2, IDESC_F16, en0);
                mma_f16_ss(tmem + 0,   dAhi0 + ks * 2, dWlo + ks * 2, IDESC_F16, 1u);
                mma_f16_ss(tmem + 128, dAhi1 + ks * 2, dWlo + ks * 2, IDESC_F16, 1u);
                mma_f16_ss(tmem + 0,   dAlo0 + ks * 2, dWhi + ks * 2, IDESC_F16, 1u);
                mma_f16_ss(tmem + 128, dAlo1 + ks * 2, dWhi + ks * 2, IDESC_F16, 1u);
            }
            asm volatile(
                "tcgen05.commit.cta_group::1.mbarrier::arrive::one.shared::cluster.b64 [%0];"
                :: "r"(sbase + 16 + p * 8) : "memory");
        }
        {
            uint32_t mb = sbase + 16 + p * 8;
            uint32_t ph = p ? phase1 : phase0;
            uint32_t done;
            asm volatile(
                "{\n\t.reg .pred q;\n\t"
                "mbarrier.try_wait.parity.shared.b64 q, [%1], %2, 0x989680;\n\t"
                "selp.b32 %0, 1, 0, q;\n\t}"
                : "=r"(done) : "r"(mb), "r"(ph) : "memory");
            while (!done) {
                asm volatile(
                    "{\n\t.reg .pred q;\n\t"
                    "mbarrier.try_wait.parity.shared.b64 q, [%1], %2, 0x989680;\n\t"
                    "selp.b32 %0, 1, 0, q;\n\t}"
                    : "=r"(done) : "r"(mb), "r"(ph) : "memory");
            }
            if (p) phase1 ^= 1; else phase0 ^= 1;
        }
        if (c + 2 < KCH)
            load_chunk(Ag, Wg, (c + 2) * 64, sbase + SMEM_HDR + p * STAGE, tid);
    }

    asm volatile("tcgen05.fence::after_thread_sync;" ::: "memory");
    {
        const int sub = tid >> 7;
        const int wiw = (tid >> 5) & 3;
        const int mrow = m0g + sub * 128 + wiw * 32 + lane;
        const uint32_t warp_off = ((uint32_t)(tid & 127) >> 5) << 21;
        const uint32_t dbase = tmem + sub * 128 + warp_off;
        if (mrow < MROWS) {
            const int t = mrow >> 5, b = mrow & 31;
            float* orow = out + (size_t)(b * T_ + t + 1) * V_ + n0;
#pragma unroll
            for (int q = 0; q < 4; q++) {
                uint32_t r[32];
                asm volatile(
                    "tcgen05.ld.sync.aligned.32x32b.x32.b32 "
                    "{%0,%1,%2,%3,%4,%5,%6,%7,%8,%9,%10,%11,%12,%13,%14,%15,"
                    "%16,%17,%18,%19,%20,%21,%22,%23,%24,%25,%26,%27,%28,%29,%30,%31}, [%32];"
                    : "=r"(r[0]), "=r"(r[1]), "=r"(r[2]), "=r"(r[3]), "=r"(r[4]), "=r"(r[5]),
                      "=r"(r[6]), "=r"(r[7]), "=r"(r[8]), "=r"(r[9]), "=r"(r[10]), "=r"(r[11]),
                      "=r"(r[12]), "=r"(r[13]), "=r"(r[14]), "=r"(r[15]), "=r"(r[16]), "=r"(r[17]),
                      "=r"(r[18]), "=r"(r[19]), "=r"(r[20]), "=r"(r[21]), "=r"(r[22]), "=r"(r[23]),
                      "=r"(r[24]), "=r"(r[25]), "=r"(r[26]), "=r"(r[27]), "=r"(r[28]), "=r"(r[29]),
                      "=r"(r[30]), "=r"(r[31])
                    : "r"(dbase + q * 32));
                asm volatile("tcgen05.wait::ld.sync.aligned;" ::: "memory");
#pragma unroll
                for (int c4 = 0; c4 < 8; c4++) {
                    const int n = q * 32 + c4 * 4;
                    float4 bb = *(const float4*)(bias + n0 + n);
                    float4 v;
                    v.x = __uint_as_float(r[c4 * 4 + 0]) + bb.x;
                    v.y = __uint_as_float(r[c4 * 4 + 1]) + bb.y;
                    v.z = __uint_as_float(r[c4 * 4 + 2]) + bb.z;
                    v.w = __uint_as_float(r[c4 * 4 + 3]) + bb.w;
                    *(float4*)(orow + n) = v;
                }
            }
        } else {
#pragma unroll
            for (int q = 0; q < 4; q++) {
                uint32_t r0;
                asm volatile("tcgen05.ld.sync.aligned.32x32b.x1.b32 {%0}, [%1];"
                             : "=r"(r0) : "r"(dbase + q * 32));
                asm volatile("tcgen05.wait::ld.sync.aligned;" ::: "memory");
            }
        }
    }
    __syncthreads();
    if (wid == 0) {
        asm volatile("tcgen05.relinquish_alloc_permit.cta_group::1.sync.aligned;" ::: "memory");
        asm volatile("tcgen05.dealloc.cta_group::1.sync.aligned.b32 %0, 512;" :: "r"(tmem));
    }
#endif  // HAS_TC
}

// ---------------- launch ----------------
extern "C" void kernel_launch(void* const* d_in, const int* in_sizes, int n_in,
                              void* d_out, int out_size)
{
    (void)in_sizes; (void)n_in; (void)out_size;
    const int*   src     = (const int*)d_in[0];
    const int*   trg     = (const int*)d_in[1];
    const float* enc_emb = (const float*)d_in[2];
    const float* dec_emb = (const float*)d_in[3];
    const float* eWih_f  = (const float*)d_in[4];
    const float* eWhh_f  = (const float*)d_in[5];
    const float* eb_f    = (const float*)d_in[6];
    const float* eWih_b  = (const float*)d_in[7];
    const float* eWhh_b  = (const float*)d_in[8];
    const float* eb_b    = (const float*)d_in[9];
    const float* dWih    = (const float*)d_in[10];
    const float* dWhh    = (const float*)d_in[11];
    const float* db      = (const float*)d_in[12];
    const float* fcW     = (const float*)d_in[13];
    const float* fcb     = (const float*)d_in[14];
    float* out = (float*)d_out;

    cudaFuncSetAttribute(enc_persist_k, cudaFuncAttributeMaxDynamicSharedMemorySize,
                         131072);                         // 128 KB
    cudaFuncSetAttribute(dec_persist_k, cudaFuncAttributeMaxDynamicSharedMemorySize,
                         196608);                         // 192 KB
    cudaFuncSetAttribute(bgemm_tc, cudaFuncAttributeMaxDynamicSharedMemorySize, SMEM_TC);

    void *p_pre_fT, *p_pre_bT, *p_dec_preT, *p_enc_ri, *p_dec_ri;
    cudaGetSymbolAddress(&p_pre_fT, g_pre_fT);
    cudaGetSymbolAddress(&p_pre_bT, g_pre_bT);
    cudaGetSymbolAddress(&p_dec_preT, g_dec_preT);
    cudaGetSymbolAddress(&p_enc_ri, g_enc_rowidx);
    cudaGetSymbolAddress(&p_dec_ri, g_dec_rowidx);

    long total = (long)B_ * V_ + 2L * H_ * B_ + (long)S_ * B_ + (long)TD * B_
               + 192 + (long)(MPAD - MROWS) * 2048;
    prep_k<<<(unsigned)((total + 255) / 256), 256>>>(src, trg, out);
    wconv_k<<<V_, 256>>>(fcW);

    sgemm3_k<<<dim3(32, 32, 3), 256>>>(
        enc_emb, dec_emb, eWih_f, eb_f, eWih_b, eb_b, dWih, db,
        (const int*)p_enc_ri, (const int*)p_dec_ri,
        (float*)p_pre_fT, (float*)p_pre_bT, (float*)p_dec_preT);

    enc_persist_k<<<128, 256, 131072>>>(eWhh_f, eWhh_b);
    dec_persist_k<<<128, 256, 196608>>>(dWhh);

    bgemm_tc<<<dim3(V_ / 128, MPAD / 256), 256, SMEM_TC>>>(fcb, out);
}